// round 15
// baseline (speedup 1.0000x reference)
#include <cuda_runtime.h>
#include <cuda_fp16.h>
#include <cstdint>
#include <cstddef>

// Problem constants
#define BB 4
#define TT 1024
#define CC 1024
#define HH 16
#define DH 64
#define FF 4096
#define MM (BB*TT)          // 4096 rows

// ---------------- scratch (device globals; no allocation allowed) ----------------
__device__ float  g_o  [(size_t)MM*CC];        // GEMM fp32 outputs (pre-LN)
__device__ float  g_x1 [(size_t)MM*CC];
__device__ float  g_x2 [(size_t)MM*CC];
__device__ __half g_xh [(size_t)MM*CC];        // half GEMM-A operands
__device__ __half g_eh [(size_t)MM*CC];
__device__ __half g_qh [(size_t)MM*CC];        // cross-attn Q (half, flash input)
__device__ __half g_ctxh[(size_t)MM*CC];
__device__ __half g_x1h[(size_t)MM*CC];
__device__ __half g_x2h[(size_t)MM*CC];
__device__ __half g_ffh[(size_t)MM*FF];        // QKV / KV / FFN1 half outputs
__device__ __half g_wth[8u*1024u*1024u + 2u*4096u*1024u];   // half weights (K-major)

// ============================ small helpers ======================================
__device__ __forceinline__ void mma_f16(float* d, const uint32_t* a, const uint32_t* b) {
    asm volatile(
        "mma.sync.aligned.m16n8k16.row.col.f32.f16.f16.f32 "
        "{%0,%1,%2,%3},{%4,%5,%6,%7},{%8,%9},{%0,%1,%2,%3};"
        : "+f"(d[0]), "+f"(d[1]), "+f"(d[2]), "+f"(d[3])
        : "r"(a[0]), "r"(a[1]), "r"(a[2]), "r"(a[3]),
          "r"(b[0]), "r"(b[1]));
}
// f16-accumulator variant (full-rate path hypothesis)
__device__ __forceinline__ void mma_f16h(uint32_t* d, const uint32_t* a, const uint32_t* b) {
    asm volatile(
        "mma.sync.aligned.m16n8k16.row.col.f16.f16.f16.f16 "
        "{%0,%1},{%2,%3,%4,%5},{%6,%7},{%0,%1};"
        : "+r"(d[0]), "+r"(d[1])
        : "r"(a[0]), "r"(a[1]), "r"(a[2]), "r"(a[3]),
          "r"(b[0]), "r"(b[1]));
}
__device__ __forceinline__ void ldsm4(uint32_t* r, uint32_t addr) {
    asm volatile("ldmatrix.sync.aligned.m8n8.x4.shared.b16 {%0,%1,%2,%3}, [%4];"
                 : "=r"(r[0]), "=r"(r[1]), "=r"(r[2]), "=r"(r[3]) : "r"(addr));
}
__device__ __forceinline__ void ldsm4t(uint32_t* r, uint32_t addr) {
    asm volatile("ldmatrix.sync.aligned.m8n8.x4.trans.shared.b16 {%0,%1,%2,%3}, [%4];"
                 : "=r"(r[0]), "=r"(r[1]), "=r"(r[2]), "=r"(r[3]) : "r"(addr));
}
__device__ __forceinline__ uint32_t smem_u32(const void* p) {
    uint32_t a;
    asm("{ .reg .u64 t; cvta.to.shared.u64 t, %1; cvt.u32.u64 %0, t; }" : "=r"(a) : "l"(p));
    return a;
}
__device__ __forceinline__ void cp16(uint32_t dst, const void* src) {
    asm volatile("cp.async.cg.shared.global [%0], [%1], 16;" :: "r"(dst), "l"(src));
}
__device__ __forceinline__ void bulk128(uint32_t dst, const void* src, uint32_t mbar) {
    asm volatile("cp.async.bulk.shared::cta.global.mbarrier::complete_tx::bytes "
                 "[%0], [%1], 128, [%2];"
                 :: "r"(dst), "l"(src), "r"(mbar) : "memory");
}
__device__ __forceinline__ void mbar_init1(uint32_t a) {
    asm volatile("mbarrier.init.shared.b64 [%0], 1;" :: "r"(a) : "memory");
}
__device__ __forceinline__ void mbar_expect(uint32_t a, uint32_t bytes) {
    asm volatile("mbarrier.arrive.expect_tx.shared.b64 _, [%0], %1;"
                 :: "r"(a), "r"(bytes) : "memory");
}
__device__ __forceinline__ void mbar_wait(uint32_t a, uint32_t ph) {
    uint32_t done;
    asm volatile("{\n\t.reg .pred p;\n\t"
                 "mbarrier.try_wait.parity.acquire.cta.shared::cta.b64 p, [%1], %2;\n\t"
                 "selp.b32 %0,1,0,p;\n\t}"
                 : "=r"(done) : "r"(a), "r"(ph) : "memory");
    if (!done) {
        asm volatile("{\n\t.reg .pred P1;\n\t"
                     "WL%=:\n\t"
                     "mbarrier.try_wait.parity.acquire.cta.shared::cta.b64 P1, [%0], %1, 0x989680;\n\t"
                     "@P1 bra.uni WD%=;\n\t"
                     "bra.uni WL%=;\n\t"
                     "WD%=:\n\t}"
                     :: "r"(a), "r"(ph) : "memory");
    }
}
__device__ __forceinline__ uint32_t packh2(float a, float b) {
    __half2 h = __floats2half2_rn(a, b);
    return *(uint32_t*)&h;
}

// =================== fp16 conversion copy (2 tensors, z-batched) =================
struct Ptr2h { const float* s[2]; __half* d[2]; };
__global__ void __launch_bounds__(256)
round2h(Ptr2h p)
{
    const float* in = p.s[blockIdx.y];
    __half* out = p.d[blockIdx.y];
    const size_t i = ((size_t)blockIdx.x * 256 + threadIdx.x) * 4;
    float4 v = *(const float4*)(in + i);
    *(__half2*)(out + i)     = __floats2half2_rn(v.x, v.y);
    *(__half2*)(out + i + 2) = __floats2half2_rn(v.z, v.w);
}

// ====================== 32x32 tiled transposes (fp16 out) ========================
struct Ptr8h { const float* s[8]; __half* d[8]; };

__global__ void __launch_bounds__(256)
transpose8h(Ptr8h ps)   // 8 square [CC x CC] weights, z selects matrix
{
    const float* in = ps.s[blockIdx.z];
    __half* out = ps.d[blockIdx.z];
    __shared__ float t[32][33];
    const int bx = blockIdx.x * 32, by = blockIdx.y * 32;
    int x = bx + threadIdx.x;
#pragma unroll
    for (int i = 0; i < 32; i += 8)
        t[threadIdx.y + i][threadIdx.x] = in[(size_t)(by + threadIdx.y + i) * CC + x];
    __syncthreads();
    x = by + threadIdx.x;
#pragma unroll
    for (int i = 0; i < 32; i += 8)
        out[(size_t)(bx + threadIdx.y + i) * CC + x] = __float2half_rn(t[threadIdx.x][threadIdx.y + i]);
}

// both FFN weight transposes in one launch (1D grid, 8192 tiles)
__global__ void __launch_bounds__(256)
transpose_w2(const float* __restrict__ Wf1, __half* __restrict__ tf1,
             const float* __restrict__ Wf2, __half* __restrict__ tf2)
{
    const int bid = blockIdx.x;
    const bool second = bid >= 4096;
    const int tile = second ? bid - 4096 : bid;
    const float* in;  __half* outp;  int R, C, bx, by;
    if (!second) { in = Wf1; outp = tf1; R = CC; C = FF; bx = (tile & 127) * 32; by = (tile >> 7) * 32; }
    else         { in = Wf2; outp = tf2; R = FF; C = CC; bx = (tile & 31)  * 32; by = (tile >> 5) * 32; }
    const int tx = threadIdx.x, ty = threadIdx.y;
    __shared__ float t[32][33];
    int x = bx + tx;
#pragma unroll
    for (int i = 0; i < 32; i += 8)
        t[ty + i][tx] = in[(size_t)(by + ty + i) * C + x];
    __syncthreads();
    x = by + tx;
#pragma unroll
    for (int i = 0; i < 32; i += 8)
        outp[(size_t)(bx + ty + i) * R + x] = __float2half_rn(t[tx][ty + i]);
}

// ================= fp16 mma.sync GEMM: C[M,N] = A[M,K] @ Bt[N,K]^T ===============
// f16-ACCUMULATOR inner loop (per-stage K=64 partial), promoted to fp32 per stage.
// Bulk-copy staging (R14). Fragment double-buffer removed (R13 null result).
#define G_LDPH 72                            // halfs per row (64 data + 8 pad)
#define G_STGH (256 * G_LDPH)                // halfs per stage (A128 + B128 rows)
#define GSMEM  (3 * G_STGH * 2 + 64)         // + 3 mbarriers (aligned)

template<bool BIAS, bool RELU, bool HOUT>
__global__ void __launch_bounds__(256, 2)
gemm_mma(const __half* __restrict__ A, const __half* __restrict__ Bt,
         const float* __restrict__ bias, void* __restrict__ Cv,
         int K, int lda, int ldb, int ldc)
{
    extern __shared__ __half smh[];
    const int bxn = blockIdx.x * 128, bym = blockIdx.y * 128;
    const int tid = threadIdx.x, wid = tid >> 5, lane = tid & 31;
    const int wr = wid >> 2, wc = wid & 3;      // 2 x 4 warps, 64x32 each
    const int g = lane >> 2, qc = lane & 3;

    const uint32_t smb = smem_u32(smh);
    const uint32_t mbar0 = smb + 3 * G_STGH * 2;

    // one 128-byte row per thread per stage: tid<128 -> A row, else B row
    const __half* gsrc = (tid < 128)
        ? (A  + (size_t)(bym + tid) * lda)
        : (Bt + (size_t)(bxn + tid - 128) * ldb);
    const uint32_t sdst = smb + (uint32_t)tid * (G_LDPH * 2);

    const int l15 = lane & 15, l7 = lane & 7;
    const uint32_t aL = smb
        + (uint32_t)(((wr * 64 + l15) * G_LDPH + (lane >> 4) * 8) * 2);
    const uint32_t bL = smb + 128 * G_LDPH * 2
        + (uint32_t)(((wc * 32 + l7 + (lane >> 4) * 8) * G_LDPH + ((lane >> 3) & 1) * 8) * 2);

    float acc[4][4][4];
#pragma unroll
    for (int i = 0; i < 4; i++)
#pragma unroll
        for (int j = 0; j < 4; j++)
#pragma unroll
            for (int r = 0; r < 4; r++) acc[i][j][r] = 0.f;

    const int nst = K >> 6;                    // K-stage = 64 halfs

    if (tid == 0) {
        mbar_init1(mbar0);
        mbar_init1(mbar0 + 8);
        mbar_init1(mbar0 + 16);
        asm volatile("fence.proxy.async.shared::cta;" ::: "memory");
    }
    __syncthreads();

    // prologue: stages 0, 1
#pragma unroll
    for (int s = 0; s < 2; s++) {
        if (tid == 0) mbar_expect(mbar0 + s * 8, 32768u);
        bulk128(sdst + s * (G_STGH * 2), gsrc + s * 64, mbar0 + s * 8);
    }

    int buf = 0, nxt = 2;      // nxt = (it+2) % 3
    int pw = 0;                // parity of stage being waited (flips on buf wrap)
    for (int it = 0; it < nst; ++it) {
        mbar_wait(mbar0 + buf * 8, pw);
        __syncthreads();
        const uint32_t aB = aL + (uint32_t)buf * G_STGH * 2;
        const uint32_t bB = bL + (uint32_t)buf * G_STGH * 2;

        // f16 stage-partial accumulators (zeroed per stage)
        uint32_t hacc[4][4][2];
#pragma unroll
        for (int mi = 0; mi < 4; mi++)
#pragma unroll
            for (int ni = 0; ni < 4; ni++) { hacc[mi][ni][0] = 0u; hacc[mi][ni][1] = 0u; }

#pragma unroll
        for (int ks = 0; ks < 4; ks++) {       // 4 x k16, f16 accumulate
            uint32_t bv_[2][4];
#pragma unroll
            for (int np = 0; np < 2; np++)
                ldsm4(bv_[np], bB + np * (16 * G_LDPH * 2) + ks * 32);
#pragma unroll
            for (int mi = 0; mi < 4; mi++) {
                uint32_t av_[4];
                ldsm4(av_, aB + mi * (16 * G_LDPH * 2) + ks * 32);
#pragma unroll
                for (int ni = 0; ni < 4; ni++)
                    mma_f16h(hacc[mi][ni], av_, &bv_[ni >> 1][(ni & 1) * 2]);
            }
        }
        // promote stage partial to fp32
#pragma unroll
        for (int mi = 0; mi < 4; mi++)
#pragma unroll
            for (int ni = 0; ni < 4; ni++) {
                float2 lo = __half22float2(*(__half2*)&hacc[mi][ni][0]);
                float2 hi = __half22float2(*(__half2*)&hacc[mi][ni][1]);
                acc[mi][ni][0] += lo.x; acc[mi][ni][1] += lo.y;
                acc[mi][ni][2] += hi.x; acc[mi][ni][3] += hi.y;
            }

        if (it + 2 < nst) {
            const int kt = it + 2;
            if (tid == 0) mbar_expect(mbar0 + nxt * 8, 32768u);
            bulk128(sdst + nxt * (G_STGH * 2), gsrc + kt * 64, mbar0 + nxt * 8);
        }
        if (buf == 2) { buf = 0; pw ^= 1; } else buf++;
        nxt = (nxt == 2) ? 0 : nxt + 1;
    }

#pragma unroll
    for (int mi = 0; mi < 4; mi++) {
        const int r = bym + wr * 64 + mi * 16 + g;
#pragma unroll
        for (int ni = 0; ni < 4; ni++) {
            const int col = bxn + wc * 32 + ni * 8 + qc * 2;
            float2 bv = make_float2(0.f, 0.f);
            if (BIAS) bv = *(const float2*)(bias + col);
            float2 v0, v1;
            v0.x = acc[mi][ni][0] + bv.x;
            v0.y = acc[mi][ni][1] + bv.y;
            v1.x = acc[mi][ni][2] + bv.x;
            v1.y = acc[mi][ni][3] + bv.y;
            if (RELU) {
                v0.x = fmaxf(v0.x, 0.f); v0.y = fmaxf(v0.y, 0.f);
                v1.x = fmaxf(v1.x, 0.f); v1.y = fmaxf(v1.y, 0.f);
            }
            if (HOUT) {
                __half* C = (__half*)Cv;
                *(__half2*)(C + (size_t)r * ldc + col)       = __floats2half2_rn(v0.x, v0.y);
                *(__half2*)(C + (size_t)(r + 8) * ldc + col) = __floats2half2_rn(v1.x, v1.y);
            } else {
                float* C = (float*)Cv;
                *(float2*)(C + (size_t)r * ldc + col)       = v0;
                *(float2*)(C + (size_t)(r + 8) * ldc + col) = v1;
            }
        }
    }
}

// ====================== flash attention (fp16 mma, ldmatrix) =====================
// (byte-identical to R14 — fp32 accumulators kept for numerics)
#define FLB_K  18432
#define FLB_V  55296
#define FLB_M  92160
#define FSMEM  (92160 + 264)

template<bool CAUSAL>
__global__ void __launch_bounds__(256, 2)
flash_k(const __half* __restrict__ Qg, const __half* __restrict__ Kg,
        const __half* __restrict__ Vg, const unsigned char* __restrict__ padg,
        __half* __restrict__ Og, int ldq, int ldk)
{
    extern __shared__ __half smh[];
    const int tid = threadIdx.x, lane = tid & 31, w = tid >> 5;
    const int g = lane >> 2, qc = lane & 3;
    const int qt = blockIdx.x;
    const int z = blockIdx.y, b = z >> 4, h = z & 15;

    const __half* Qp = Qg + (size_t)b * TT * ldq + h * 64;
    const __half* Kp = Kg + (size_t)b * TT * ldk + h * 64;
    const __half* Vp = Vg + (size_t)b * TT * ldk + h * 64;   // same layout as K
    const unsigned char* padp = padg + (size_t)b * TT;
    __half* Op = Og + (size_t)b * TT * CC + h * 64;

    const uint32_t sQa = smem_u32(smh);
    const uint32_t sKa = sQa + FLB_K;
    const uint32_t sVa = sQa + FLB_V;
    uint32_t* sMskp = (uint32_t*)((char*)smh + FLB_M);

    const int l15 = lane & 15, l7 = lane & 7;
    const uint32_t qL = sQa + (uint32_t)(((w * 16 + l15) * 72 + (lane >> 4) * 8) * 2);
    const uint32_t kL = sKa + (uint32_t)(((l7 + (lane >> 4) * 8) * 72 + ((lane >> 3) & 1) * 8) * 2);
    const uint32_t vL = sVa + (uint32_t)(((l7 + ((lane >> 3) & 1) * 8) * 72 + (lane >> 4) * 8) * 2);

    const int nkt = CAUSAL ? qt + 1 : (TT / 128);

    {   // Q tile: 128 rows x 64 halfs, rows padded to 72 halfs (144 B)
        const __half* qs = Qp + (size_t)(qt * 128 + (tid >> 1)) * ldq + (tid & 1) * 32;
        uint32_t qd = sQa + (tid >> 1) * 144 + (tid & 1) * 64;
#pragma unroll
        for (int j = 0; j < 4; j++) cp16(qd + j * 16, qs + j * 8);
    }
    auto issue_kv = [&](int kt, int buf) {
        const __half* ks = Kp + (size_t)(kt * 128 + (tid >> 1)) * ldk + (tid & 1) * 32;
        uint32_t kd = sKa + buf * 18432u + (tid >> 1) * 144 + (tid & 1) * 64;
#pragma unroll
        for (int j = 0; j < 4; j++) cp16(kd + j * 16, ks + j * 8);
        const __half* vs = Vp + (size_t)(kt * 128 + (tid >> 1)) * ldk + (tid & 1) * 32;
        uint32_t vd = sVa + buf * 18432u + (tid >> 1) * 144 + (tid & 1) * 64;
#pragma unroll
        for (int j = 0; j < 4; j++) cp16(vd + j * 16, vs + j * 8);
        if (tid < 32) {
            uint32_t mv = *(const uint32_t*)(padp + (size_t)kt * 128 + tid * 4);
            sMskp[buf * 32 + tid] = mv;
            uint32_t f = __reduce_or_sync(0xffffffffu, mv);
            if (tid == 0) sMskp[64 + buf] = f;
        }
    };
    issue_kv(0, 0);
    asm volatile("cp.async.commit_group;" ::: "memory");

    float m0 = -INFINITY, m1 = -INFINITY, l0 = 0.f, l1 = 0.f;
    float oacc[8][4];
#pragma unroll
    for (int j = 0; j < 8; j++)
#pragma unroll
        for (int r = 0; r < 4; r++) oacc[j][r] = 0.f;

    const int r0 = w * 16 + g, r1 = r0 + 8;

    for (int kt = 0; kt < nkt; ++kt) {
        const int buf = kt & 1;
        if (kt + 1 < nkt) {
            issue_kv(kt + 1, buf ^ 1);
            asm volatile("cp.async.commit_group;" ::: "memory");
            asm volatile("cp.async.wait_group 1;" ::: "memory");
        } else {
            asm volatile("cp.async.wait_group 0;" ::: "memory");
        }
        __syncthreads();

        float sacc[16][4];
#pragma unroll
        for (int ni = 0; ni < 16; ni++)
#pragma unroll
            for (int r = 0; r < 4; r++) sacc[ni][r] = 0.f;
        {
            const uint32_t kB = kL + buf * 18432u;
#pragma unroll
            for (int ks = 0; ks < 4; ks++) {
                uint32_t aq[4];
                ldsm4(aq, qL + ks * 32);
#pragma unroll
                for (int np = 0; np < 8; np++) {
                    uint32_t kv4[4];
                    ldsm4(kv4, kB + np * (16 * 144) + ks * 32);
                    mma_f16(sacc[2 * np],     aq, kv4);
                    mma_f16(sacc[2 * np + 1], aq, kv4 + 2);
                }
            }
        }

        const uint32_t pf = sMskp[64 + buf];
        const unsigned char* mb = (const unsigned char*)(sMskp + buf * 32);
        float tm0 = -INFINITY, tm1 = -INFINITY;
#pragma unroll
        for (int ni = 0; ni < 16; ni++) {
            float s0 = sacc[ni][0] * 0.125f, s1 = sacc[ni][1] * 0.125f;
            float s2 = sacc[ni][2] * 0.125f, s3 = sacc[ni][3] * 0.125f;
            const int c0 = ni * 8 + qc * 2;
            if (CAUSAL && kt == qt) {
                if (c0     > r0) s0 = -INFINITY;
                if (c0 + 1 > r0) s1 = -INFINITY;
                if (c0     > r1) s2 = -INFINITY;
                if (c0 + 1 > r1) s3 = -INFINITY;
            }
            if (pf) {
                if (mb[c0])     { s0 = -INFINITY; s2 = -INFINITY; }
                if (mb[c0 + 1]) { s1 = -INFINITY; s3 = -INFINITY; }
            }
            sacc[ni][0] = s0; sacc[ni][1] = s1; sacc[ni][2] = s2; sacc[ni][3] = s3;
            tm0 = fmaxf(tm0, fmaxf(s0, s1));
            tm1 = fmaxf(tm1, fmaxf(s2, s3));
        }
        tm0 = fmaxf(tm0, __shfl_xor_sync(0xffffffffu, tm0, 1));
        tm0 = fmaxf(tm0, __shfl_xor_sync(0xffffffffu, tm0, 2));
        tm1 = fmaxf(tm1, __shfl_xor_sync(0xffffffffu, tm1, 1));
        tm1 = fmaxf(tm1, __shfl_xor_sync(0xffffffffu, tm1, 2));
        const float mn0 = fmaxf(m0, tm0), mn1 = fmaxf(m1, tm1);

        float sum0 = 0.f, sum1 = 0.f;
#pragma unroll
        for (int ni = 0; ni < 16; ni++) {
            float p0 = __expf(sacc[ni][0] - mn0);
            float p1 = __expf(sacc[ni][1] - mn0);
            float p2 = __expf(sacc[ni][2] - mn1);
            float p3 = __expf(sacc[ni][3] - mn1);
            sacc[ni][0] = p0; sacc[ni][1] = p1; sacc[ni][2] = p2; sacc[ni][3] = p3;
            sum0 += p0 + p1; sum1 += p2 + p3;
        }
        sum0 += __shfl_xor_sync(0xffffffffu, sum0, 1);
        sum0 += __shfl_xor_sync(0xffffffffu, sum0, 2);
        sum1 += __shfl_xor_sync(0xffffffffu, sum1, 1);
        sum1 += __shfl_xor_sync(0xffffffffu, sum1, 2);

        const float sc0 = __expf(m0 - mn0), sc1 = __expf(m1 - mn1);
        l0 = l0 * sc0 + sum0;  l1 = l1 * sc1 + sum1;
        m0 = mn0;  m1 = mn1;
#pragma unroll
        for (int nj = 0; nj < 8; nj++) {
            oacc[nj][0] *= sc0; oacc[nj][1] *= sc0;
            oacc[nj][2] *= sc1; oacc[nj][3] *= sc1;
        }

        {
            const uint32_t vB = vL + buf * 18432u;
#pragma unroll
            for (int k2 = 0; k2 < 8; k2++) {
                uint32_t pa[4];
                pa[0] = packh2(sacc[2 * k2][0],     sacc[2 * k2][1]);
                pa[1] = packh2(sacc[2 * k2][2],     sacc[2 * k2][3]);
                pa[2] = packh2(sacc[2 * k2 + 1][0], sacc[2 * k2 + 1][1]);
                pa[3] = packh2(sacc[2 * k2 + 1][2], sacc[2 * k2 + 1][3]);
#pragma unroll
                for (int np = 0; np < 4; np++) {
                    uint32_t vv[4];
                    ldsm4t(vv, vB + k2 * (16 * 144) + np * 32);
                    mma_f16(oacc[2 * np],     pa, vv);
                    mma_f16(oacc[2 * np + 1], pa, vv + 2);
                }
            }
        }
        __syncthreads();
    }

    const float inv0 = 1.f / l0, inv1 = 1.f / l1;
    __half* orow0 = Op + (size_t)(qt * 128 + r0) * CC;
    __half* orow1 = orow0 + 8 * CC;
#pragma unroll
    for (int nj = 0; nj < 8; nj++) {
        *(__half2*)(orow0 + nj * 8 + qc * 2) =
            __floats2half2_rn(oacc[nj][0] * inv0, oacc[nj][1] * inv0);
        *(__half2*)(orow1 + nj * 8 + qc * 2) =
            __floats2half2_rn(oacc[nj][2] * inv1, oacc[nj][3] * inv1);
    }
}

// ============================ layernorm ==========================================
__device__ __forceinline__ float warpSum(float v) {
#pragma unroll
    for (int o = 16; o; o >>= 1) v += __shfl_xor_sync(0xffffffffu, v, o);
    return v;
}

template<bool DUALH>
__global__ void __launch_bounds__(256)
add_ln(const float* __restrict__ X, const float* __restrict__ R,
       const float* __restrict__ g, const float* __restrict__ be,
       float* __restrict__ out, __half* __restrict__ outh)
{
    const size_t row = blockIdx.x;
    const int tid = threadIdx.x;
    const int col = tid * 4;
    float4 xv = *(const float4*)(X + row * CC + col);
    float4 rv = *(const float4*)(R + row * CC + col);
    float4 v;
    v.x = xv.x + rv.x; v.y = xv.y + rv.y; v.z = xv.z + rv.z; v.w = xv.w + rv.w;

    __shared__ float sh1[8], sh2[8];
    float s = (v.x + v.y) + (v.z + v.w);
    float sq = v.x * v.x + v.y * v.y + v.z * v.z + v.w * v.w;
    s = warpSum(s); sq = warpSum(sq);
    if ((tid & 31) == 0) { sh1[tid >> 5] = s; sh2[tid >> 5] = sq; }
    __syncthreads();
    s  = (sh1[0] + sh1[1]) + (sh1[2] + sh1[3]) + (sh1[4] + sh1[5]) + (sh1[6] + sh1[7]);
    sq = (sh2[0] + sh2[1]) + (sh2[2] + sh2[3]) + (sh2[4] + sh2[5]) + (sh2[6] + sh2[7]);
    const float mean = s * (1.0f / CC);
    const float var = sq * (1.0f / CC) - mean * mean;
    const float rstd = rsqrtf(var + 1e-5f);

    float4 gg = *(const float4*)(g + col);
    float4 bb = *(const float4*)(be + col);
    float4 o;
    o.x = (v.x - mean) * rstd * gg.x + bb.x;
    o.y = (v.y - mean) * rstd * gg.y + bb.y;
    o.z = (v.z - mean) * rstd * gg.z + bb.z;
    o.w = (v.w - mean) * rstd * gg.w + bb.w;
    *(float4*)(out + row * CC + col) = o;
    if (DUALH) {
        *(__half2*)(outh + row * CC + col)     = __floats2half2_rn(o.x, o.y);
        *(__half2*)(outh + row * CC + col + 2) = __floats2half2_rn(o.z, o.w);
    }
}

// ------------------------------- launcher ---------------------------------------
extern "C" void kernel_launch(void* const* d_in, const int* in_sizes, int n_in,
                              void* d_out, int out_size)
{
    const float* x    = (const float*)d_in[0];
    const float* enc  = (const float*)d_in[1];
    const unsigned char* tmask = (const unsigned char*)d_in[2];
    const unsigned char* smask = (const unsigned char*)d_in[3];
    const float* Wq1 = (const float*)d_in[4];
    const float* Wk1 = (const float*)d_in[5];
    const float* Wv1 = (const float*)d_in[6];
    const float* Wo1 = (const float*)d_in[7];
    const float* ln1g = (const float*)d_in[8];
    const float* ln1b = (const float*)d_in[9];
    const float* Wq2 = (const float*)d_in[10];
    const float* Wk2 = (const float*)d_in[11];
    const float* Wv2 = (const float*)d_in[12];
    const float* Wo2 = (const float*)d_in[13];
    const float* ln2g = (const float*)d_in[14];
    const float* ln2b = (const float*)d_in[15];
    const float* Wf1 = (const float*)d_in[16];
    const float* bf1 = (const float*)d_in[17];
    const float* Wf2 = (const float*)d_in[18];
    const float* bf2 = (const float*)d_in[19];
    const float* ln3g = (const float*)d_in[20];
    const float* ln3b = (const float*)d_in[21];
    float* out = (float*)d_out;

    float *go, *gx1, *gx2;
    __half *gxh, *geh, *gqh, *gctxh, *gx1h, *gx2h, *gffh, *gwth;
    cudaGetSymbolAddress((void**)&go,  g_o);
    cudaGetSymbolAddress((void**)&gx1, g_x1);
    cudaGetSymbolAddress((void**)&gx2, g_x2);
    cudaGetSymbolAddress((void**)&gxh, g_xh);
    cudaGetSymbolAddress((void**)&geh, g_eh);
    cudaGetSymbolAddress((void**)&gqh, g_qh);
    cudaGetSymbolAddress((void**)&gctxh, g_ctxh);
    cudaGetSymbolAddress((void**)&gx1h, g_x1h);
    cudaGetSymbolAddress((void**)&gx2h, g_x2h);
    cudaGetSymbolAddress((void**)&gffh, g_ffh);
    cudaGetSymbolAddress((void**)&gwth, g_wth);

    __half* tq1 = gwth + 0u * 1048576u;   // tq1,tk1,tv1 contiguous -> [3072,1024]
    __half* tk1 = gwth + 1u * 1048576u;
    __half* tv1 = gwth + 2u * 1048576u;
    __half* to1 = gwth + 3u * 1048576u;
    __half* tq2 = gwth + 4u * 1048576u;
    __half* tk2 = gwth + 5u * 1048576u;   // tk2,tv2 contiguous -> [2048,1024]
    __half* tv2 = gwth + 6u * 1048576u;
    __half* to2 = gwth + 7u * 1048576u;
    __half* tf1 = gwth + 8u * 1048576u;              // [F, C]
    __half* tf2 = gwth + 8u * 1048576u + 4194304u;   // [C, F]

    auto* kProj  = gemm_mma<false, false, false>;   // fp32 out (-> add_ln)
    auto* kProjH = gemm_mma<false, false, true >;   // half out (-> flash / GEMM-A)
    auto* kFfn1  = gemm_mma<true,  true,  true >;   // bias+relu, half out
    auto* kFfn2  = gemm_mma<true,  false, false>;
    cudaFuncSetAttribute(kProj,  cudaFuncAttributeMaxDynamicSharedMemorySize, GSMEM);
    cudaFuncSetAttribute(kProjH, cudaFuncAttributeMaxDynamicSharedMemorySize, GSMEM);
    cudaFuncSetAttribute(kFfn1,  cudaFuncAttributeMaxDynamicSharedMemorySize, GSMEM);
    cudaFuncSetAttribute(kFfn2,  cudaFuncAttributeMaxDynamicSharedMemorySize, GSMEM);
    cudaFuncSetAttribute(flash_k<true>,  cudaFuncAttributeMaxDynamicSharedMemorySize, FSMEM);
    cudaFuncSetAttribute(flash_k<false>, cudaFuncAttributeMaxDynamicSharedMemorySize, FSMEM);

    const dim3 blk(256);
    const dim3 tblk(32, 8);

    // ---- fp16 conversion of external GEMM-A inputs (1 launch) ----
    Ptr2h p2;
    p2.s[0] = x;   p2.d[0] = gxh;
    p2.s[1] = enc; p2.d[1] = geh;
    round2h<<<dim3(MM * CC / 1024, 2), blk>>>(p2);

    // ---- weight transposes (K-major, fp16 B operands) ----
    Ptr8h p8;
    p8.s[0] = Wq1; p8.d[0] = tq1;  p8.s[1] = Wk1; p8.d[1] = tk1;
    p8.s[2] = Wv1; p8.d[2] = tv1;  p8.s[3] = Wo1; p8.d[3] = to1;
    p8.s[4] = Wq2; p8.d[4] = tq2;  p8.s[5] = Wk2; p8.d[5] = tk2;
    p8.s[6] = Wv2; p8.d[6] = tv2;  p8.s[7] = Wo2; p8.d[7] = to2;
    transpose8h<<<dim3(CC/32, CC/32, 8), tblk>>>(p8);
    transpose_w2<<<8192, tblk>>>(Wf1, tf1, Wf2, tf2);

    const dim3 gQKV(3072/128, MM/128);   // (24, 32) fused self QKV
    const dim3 gKV (2048/128, MM/128);   // (16, 32) fused cross KV
    const dim3 gP  (CC/128,   MM/128);   // (8, 32)
    const dim3 gF1 (FF/128,   MM/128);   // (32, 32)
    const dim3 gFl (TT/128, BB*HH);      // (8, 64)
    const int nLn = MM;

    // ---- self-attention (causal) ----
    kProjH<<<gQKV, blk, GSMEM>>>(gxh, tq1, nullptr, gffh, CC, CC, CC, 3072);
    flash_k<true><<<gFl, blk, FSMEM>>>(gffh, gffh + 1024, gffh + 2048, tmask, gctxh, 3072, 3072);
    kProj<<<gP, blk, GSMEM>>>(gctxh, to1, nullptr, go, CC, CC, CC, CC);
    add_ln<true><<<nLn, blk>>>(x, go, ln1g, ln1b, gx1, gx1h);

    // ---- cross-attention ----
    kProjH<<<gP,  blk, GSMEM>>>(gx1h, tq2, nullptr, gqh, CC, CC, CC, CC);
    kProjH<<<gKV, blk, GSMEM>>>(geh, tk2, nullptr, gffh, CC, CC, CC, 2048);
    flash_k<false><<<gFl, blk, FSMEM>>>(gqh, gffh, gffh + 1024, smask, gctxh, CC, 2048);
    kProj<<<gP, blk, GSMEM>>>(gctxh, to2, nullptr, go, CC, CC, CC, CC);
    add_ln<true><<<nLn, blk>>>(gx1, go, ln2g, ln2b, gx2, gx2h);

    // ---- FFN ----
    kFfn1<<<gF1, blk, GSMEM>>>(gx2h, tf1, bf1, gffh, CC, CC, CC, FF);
    kFfn2<<<gP,  blk, GSMEM>>>(gffh, tf2, bf2, go, FF, FF, FF, CC);
    add_ln<false><<<nLn, blk>>>(gx2, go, ln3g, ln3b, out, nullptr);
}

// round 16
// speedup vs baseline: 1.0309x; 1.0309x over previous
#include <cuda_runtime.h>
#include <cuda_fp16.h>
#include <cstdint>
#include <cstddef>

// Problem constants
#define BB 4
#define TT 1024
#define CC 1024
#define HH 16
#define DH 64
#define FF 4096
#define MM (BB*TT)          // 4096 rows

// ---------------- scratch (device globals; no allocation allowed) ----------------
__device__ float  g_o  [(size_t)MM*CC];        // GEMM fp32 outputs (pre-LN)
__device__ float  g_x1 [(size_t)MM*CC];
__device__ float  g_x2 [(size_t)MM*CC];
__device__ __half g_xh [(size_t)MM*CC];        // half GEMM-A operands
__device__ __half g_eh [(size_t)MM*CC];
__device__ __half g_qh [(size_t)MM*CC];        // cross-attn Q (half, flash input)
__device__ __half g_ctxh[(size_t)MM*CC];
__device__ __half g_x1h[(size_t)MM*CC];
__device__ __half g_x2h[(size_t)MM*CC];
__device__ __half g_ffh[(size_t)MM*FF];        // QKV / KV / FFN1 half outputs
__device__ __half g_wth[8u*1024u*1024u + 2u*4096u*1024u];   // half weights (K-major)

// ============================ small helpers ======================================
__device__ __forceinline__ void mma_f16(float* d, const uint32_t* a, const uint32_t* b) {
    asm volatile(
        "mma.sync.aligned.m16n8k16.row.col.f32.f16.f16.f32 "
        "{%0,%1,%2,%3},{%4,%5,%6,%7},{%8,%9},{%0,%1,%2,%3};"
        : "+f"(d[0]), "+f"(d[1]), "+f"(d[2]), "+f"(d[3])
        : "r"(a[0]), "r"(a[1]), "r"(a[2]), "r"(a[3]),
          "r"(b[0]), "r"(b[1]));
}
__device__ __forceinline__ void ldsm4(uint32_t* r, uint32_t addr) {
    asm volatile("ldmatrix.sync.aligned.m8n8.x4.shared.b16 {%0,%1,%2,%3}, [%4];"
                 : "=r"(r[0]), "=r"(r[1]), "=r"(r[2]), "=r"(r[3]) : "r"(addr));
}
__device__ __forceinline__ void ldsm4t(uint32_t* r, uint32_t addr) {
    asm volatile("ldmatrix.sync.aligned.m8n8.x4.trans.shared.b16 {%0,%1,%2,%3}, [%4];"
                 : "=r"(r[0]), "=r"(r[1]), "=r"(r[2]), "=r"(r[3]) : "r"(addr));
}
__device__ __forceinline__ uint32_t smem_u32(const void* p) {
    uint32_t a;
    asm("{ .reg .u64 t; cvta.to.shared.u64 t, %1; cvt.u32.u64 %0, t; }" : "=r"(a) : "l"(p));
    return a;
}
__device__ __forceinline__ void cp16(uint32_t dst, const void* src) {
    asm volatile("cp.async.cg.shared.global [%0], [%1], 16;" :: "r"(dst), "l"(src));
}
__device__ __forceinline__ void bulk128(uint32_t dst, const void* src, uint32_t mbar) {
    asm volatile("cp.async.bulk.shared::cta.global.mbarrier::complete_tx::bytes "
                 "[%0], [%1], 128, [%2];"
                 :: "r"(dst), "l"(src), "r"(mbar) : "memory");
}
__device__ __forceinline__ void mbar_init1(uint32_t a) {
    asm volatile("mbarrier.init.shared.b64 [%0], 1;" :: "r"(a) : "memory");
}
__device__ __forceinline__ void mbar_expect(uint32_t a, uint32_t bytes) {
    asm volatile("mbarrier.arrive.expect_tx.shared.b64 _, [%0], %1;"
                 :: "r"(a), "r"(bytes) : "memory");
}
__device__ __forceinline__ void mbar_wait(uint32_t a, uint32_t ph) {
    uint32_t done;
    asm volatile("{\n\t.reg .pred p;\n\t"
                 "mbarrier.try_wait.parity.acquire.cta.shared::cta.b64 p, [%1], %2;\n\t"
                 "selp.b32 %0,1,0,p;\n\t}"
                 : "=r"(done) : "r"(a), "r"(ph) : "memory");
    if (!done) {
        asm volatile("{\n\t.reg .pred P1;\n\t"
                     "WL%=:\n\t"
                     "mbarrier.try_wait.parity.acquire.cta.shared::cta.b64 P1, [%0], %1, 0x989680;\n\t"
                     "@P1 bra.uni WD%=;\n\t"
                     "bra.uni WL%=;\n\t"
                     "WD%=:\n\t}"
                     :: "r"(a), "r"(ph) : "memory");
    }
}
__device__ __forceinline__ uint32_t packh2(float a, float b) {
    __half2 h = __floats2half2_rn(a, b);
    return *(uint32_t*)&h;
}

// =================== fp16 conversion copy (2 tensors, z-batched) =================
struct Ptr2h { const float* s[2]; __half* d[2]; };
__global__ void __launch_bounds__(256)
round2h(Ptr2h p)
{
    const float* in = p.s[blockIdx.y];
    __half* out = p.d[blockIdx.y];
    const size_t i = ((size_t)blockIdx.x * 256 + threadIdx.x) * 4;
    float4 v = *(const float4*)(in + i);
    *(__half2*)(out + i)     = __floats2half2_rn(v.x, v.y);
    *(__half2*)(out + i + 2) = __floats2half2_rn(v.z, v.w);
}

// ====================== 32x32 tiled transposes (fp16 out) ========================
struct Ptr8h { const float* s[8]; __half* d[8]; };

__global__ void __launch_bounds__(256)
transpose8h(Ptr8h ps)   // 8 square [CC x CC] weights, z selects matrix
{
    const float* in = ps.s[blockIdx.z];
    __half* out = ps.d[blockIdx.z];
    __shared__ float t[32][33];
    const int bx = blockIdx.x * 32, by = blockIdx.y * 32;
    int x = bx + threadIdx.x;
#pragma unroll
    for (int i = 0; i < 32; i += 8)
        t[threadIdx.y + i][threadIdx.x] = in[(size_t)(by + threadIdx.y + i) * CC + x];
    __syncthreads();
    x = by + threadIdx.x;
#pragma unroll
    for (int i = 0; i < 32; i += 8)
        out[(size_t)(bx + threadIdx.y + i) * CC + x] = __float2half_rn(t[threadIdx.x][threadIdx.y + i]);
}

// both FFN weight transposes in one launch (1D grid, 8192 tiles)
__global__ void __launch_bounds__(256)
transpose_w2(const float* __restrict__ Wf1, __half* __restrict__ tf1,
             const float* __restrict__ Wf2, __half* __restrict__ tf2)
{
    const int bid = blockIdx.x;
    const bool second = bid >= 4096;
    const int tile = second ? bid - 4096 : bid;
    const float* in;  __half* outp;  int R, C, bx, by;
    if (!second) { in = Wf1; outp = tf1; R = CC; C = FF; bx = (tile & 127) * 32; by = (tile >> 7) * 32; }
    else         { in = Wf2; outp = tf2; R = FF; C = CC; bx = (tile & 31)  * 32; by = (tile >> 5) * 32; }
    const int tx = threadIdx.x, ty = threadIdx.y;
    __shared__ float t[32][33];
    int x = bx + tx;
#pragma unroll
    for (int i = 0; i < 32; i += 8)
        t[ty + i][tx] = in[(size_t)(by + ty + i) * C + x];
    __syncthreads();
    x = by + tx;
#pragma unroll
    for (int i = 0; i < 32; i += 8)
        outp[(size_t)(bx + ty + i) * R + x] = __float2half_rn(t[tx][ty + i]);
}

// ================= persistent fp16 mma.sync GEMM =================================
// C[M,N] = A[M,K] @ Bt[N,K]^T, fp32 accum. Persistent CTAs: each walks tiles
// blockIdx.x + k*gridDim.x with a CONTINUOUS 3-slot bulk-copy pipeline across
// tile boundaries (no per-tile drain/fill, no wave-quantization tails).
#define G_LDPH 72                            // halfs per row (64 data + 8 pad)
#define G_STGH (256 * G_LDPH)                // halfs per stage (A128 + B128 rows)
#define GSMEM  (3 * G_STGH * 2 + 64)         // + 3 mbarriers (aligned)

template<bool BIAS, bool RELU, bool HOUT>
__global__ void __launch_bounds__(256, 2)
gemm_mma(const __half* __restrict__ A, const __half* __restrict__ Bt,
         const float* __restrict__ bias, void* __restrict__ Cv,
         int K, int lda, int ldb, int ldc, int nbx, int ntiles)
{
    extern __shared__ __half smh[];
    const int tid = threadIdx.x, wid = tid >> 5, lane = tid & 31;
    const int wr = wid >> 2, wc = wid & 3;      // 2 x 4 warps, 64x32 each
    const int g = lane >> 2, qc = lane & 3;

    const uint32_t smb = smem_u32(smh);
    const uint32_t mbar0 = smb + 3 * G_STGH * 2;
    const uint32_t sdst = smb + (uint32_t)tid * (G_LDPH * 2);

    const int l15 = lane & 15, l7 = lane & 7;
    const uint32_t aL = smb
        + (uint32_t)(((wr * 64 + l15) * G_LDPH + (lane >> 4) * 8) * 2);
    const uint32_t bL = smb + 128 * G_LDPH * 2
        + (uint32_t)(((wc * 32 + l7 + (lane >> 4) * 8) * G_LDPH + ((lane >> 3) & 1) * 8) * 2);

    const int nst = K >> 6;                    // stages per tile (K-stage = 64 halfs)
    const int nmy = (ntiles - (int)blockIdx.x + (int)gridDim.x - 1) / (int)gridDim.x;
    if (nmy <= 0) return;
    const int S = nmy * nst;                   // total stages for this CTA

    if (tid == 0) {
        mbar_init1(mbar0);
        mbar_init1(mbar0 + 8);
        mbar_init1(mbar0 + 16);
        asm volatile("fence.proxy.async.shared::cta;" ::: "memory");
    }
    __syncthreads();

    // ---- issue cursor (tile ti, stage ki) ----
    int ti = blockIdx.x, ki = 0;
    const __half* gsrc;
    {
        const int bx = (ti % nbx) << 7, by = (ti / nbx) << 7;
        gsrc = (tid < 128) ? (A  + (size_t)(by + tid) * lda)
                           : (Bt + (size_t)(bx + tid - 128) * ldb);
    }
    auto issue = [&](int slot) {
        if (tid == 0) mbar_expect(mbar0 + slot * 8, 32768u);
        bulk128(sdst + slot * (G_STGH * 2), gsrc + ki * 64, mbar0 + slot * 8);
        if (++ki == nst) {
            ki = 0;
            ti += gridDim.x;
            if (ti < ntiles) {
                const int bx = (ti % nbx) << 7, by = (ti / nbx) << 7;
                gsrc = (tid < 128) ? (A  + (size_t)(by + tid) * lda)
                                   : (Bt + (size_t)(bx + tid - 128) * ldb);
            }
        }
    };

    // prologue: stages 0, 1 into slots 0, 1
    issue(0);
    if (S > 1) issue(1);

    // ---- compute cursor ----
    int tc = blockIdx.x, kc = 0;
    int bxc = (tc % nbx) << 7, byc = (tc / nbx) << 7;
    int slot = 0;
    int ph0 = 0, ph1 = 0, ph2 = 0;

    float acc[4][4][4];
#pragma unroll
    for (int i = 0; i < 4; i++)
#pragma unroll
        for (int j = 0; j < 4; j++)
#pragma unroll
            for (int r = 0; r < 4; r++) acc[i][j][r] = 0.f;

    for (int j = 0; j < S; ++j) {
        if (slot == 0)      { mbar_wait(mbar0,      ph0); ph0 ^= 1; }
        else if (slot == 1) { mbar_wait(mbar0 + 8,  ph1); ph1 ^= 1; }
        else                { mbar_wait(mbar0 + 16, ph2); ph2 ^= 1; }
        __syncthreads();

        const uint32_t aB = aL + (uint32_t)slot * G_STGH * 2;
        const uint32_t bB = bL + (uint32_t)slot * G_STGH * 2;
#pragma unroll
        for (int ks = 0; ks < 4; ks++) {       // 4 x k16, fp32 accumulate
            uint32_t av_[4][4], bv_[2][4];
#pragma unroll
            for (int mi = 0; mi < 4; mi++)
                ldsm4(av_[mi], aB + mi * (16 * G_LDPH * 2) + ks * 32);
#pragma unroll
            for (int np = 0; np < 2; np++)
                ldsm4(bv_[np], bB + np * (16 * G_LDPH * 2) + ks * 32);
#pragma unroll
            for (int mi = 0; mi < 4; mi++)
#pragma unroll
                for (int ni = 0; ni < 4; ni++)
                    mma_f16(acc[mi][ni], av_[mi], &bv_[ni >> 1][(ni & 1) * 2]);
        }

        // issue stage j+2 into slot (slot+2)%3 — WAR safe: all threads passed
        // this iteration's __syncthreads, so stage j-1 (same slot) is fully read.
        if (j + 2 < S) issue(slot == 0 ? 2 : slot - 1);

        // tile finished? epilogue + reset
        if (++kc == nst) {
#pragma unroll
            for (int mi = 0; mi < 4; mi++) {
                const int r = byc + wr * 64 + mi * 16 + g;
#pragma unroll
                for (int ni = 0; ni < 4; ni++) {
                    const int col = bxc + wc * 32 + ni * 8 + qc * 2;
                    float2 bv = make_float2(0.f, 0.f);
                    if (BIAS) bv = *(const float2*)(bias + col);
                    float2 v0, v1;
                    v0.x = acc[mi][ni][0] + bv.x;
                    v0.y = acc[mi][ni][1] + bv.y;
                    v1.x = acc[mi][ni][2] + bv.x;
                    v1.y = acc[mi][ni][3] + bv.y;
                    if (RELU) {
                        v0.x = fmaxf(v0.x, 0.f); v0.y = fmaxf(v0.y, 0.f);
                        v1.x = fmaxf(v1.x, 0.f); v1.y = fmaxf(v1.y, 0.f);
                    }
                    if (HOUT) {
                        __half* C = (__half*)Cv;
                        *(__half2*)(C + (size_t)r * ldc + col)       = __floats2half2_rn(v0.x, v0.y);
                        *(__half2*)(C + (size_t)(r + 8) * ldc + col) = __floats2half2_rn(v1.x, v1.y);
                    } else {
                        float* C = (float*)Cv;
                        *(float2*)(C + (size_t)r * ldc + col)       = v0;
                        *(float2*)(C + (size_t)(r + 8) * ldc + col) = v1;
                    }
                }
            }
            kc = 0;
            tc += gridDim.x;
            if (tc < ntiles) { bxc = (tc % nbx) << 7; byc = (tc / nbx) << 7; }
#pragma unroll
            for (int i = 0; i < 4; i++)
#pragma unroll
                for (int j2 = 0; j2 < 4; j2++)
#pragma unroll
                    for (int r = 0; r < 4; r++) acc[i][j2][r] = 0.f;
        }
        slot = (slot == 2) ? 0 : slot + 1;
    }
}

// ====================== flash attention (fp16 mma, ldmatrix) =====================
// (byte-identical to R14 — passing 827us config)
#define FLB_K  18432
#define FLB_V  55296
#define FLB_M  92160
#define FSMEM  (92160 + 264)

template<bool CAUSAL>
__global__ void __launch_bounds__(256, 2)
flash_k(const __half* __restrict__ Qg, const __half* __restrict__ Kg,
        const __half* __restrict__ Vg, const unsigned char* __restrict__ padg,
        __half* __restrict__ Og, int ldq, int ldk)
{
    extern __shared__ __half smh[];
    const int tid = threadIdx.x, lane = tid & 31, w = tid >> 5;
    const int g = lane >> 2, qc = lane & 3;
    const int qt = blockIdx.x;
    const int z = blockIdx.y, b = z >> 4, h = z & 15;

    const __half* Qp = Qg + (size_t)b * TT * ldq + h * 64;
    const __half* Kp = Kg + (size_t)b * TT * ldk + h * 64;
    const __half* Vp = Vg + (size_t)b * TT * ldk + h * 64;   // same layout as K
    const unsigned char* padp = padg + (size_t)b * TT;
    __half* Op = Og + (size_t)b * TT * CC + h * 64;

    const uint32_t sQa = smem_u32(smh);
    const uint32_t sKa = sQa + FLB_K;
    const uint32_t sVa = sQa + FLB_V;
    uint32_t* sMskp = (uint32_t*)((char*)smh + FLB_M);

    const int l15 = lane & 15, l7 = lane & 7;
    const uint32_t qL = sQa + (uint32_t)(((w * 16 + l15) * 72 + (lane >> 4) * 8) * 2);
    const uint32_t kL = sKa + (uint32_t)(((l7 + (lane >> 4) * 8) * 72 + ((lane >> 3) & 1) * 8) * 2);
    const uint32_t vL = sVa + (uint32_t)(((l7 + ((lane >> 3) & 1) * 8) * 72 + (lane >> 4) * 8) * 2);

    const int nkt = CAUSAL ? qt + 1 : (TT / 128);

    {   // Q tile: 128 rows x 64 halfs, rows padded to 72 halfs (144 B)
        const __half* qs = Qp + (size_t)(qt * 128 + (tid >> 1)) * ldq + (tid & 1) * 32;
        uint32_t qd = sQa + (tid >> 1) * 144 + (tid & 1) * 64;
#pragma unroll
        for (int j = 0; j < 4; j++) cp16(qd + j * 16, qs + j * 8);
    }
    auto issue_kv = [&](int kt, int buf) {
        const __half* ks = Kp + (size_t)(kt * 128 + (tid >> 1)) * ldk + (tid & 1) * 32;
        uint32_t kd = sKa + buf * 18432u + (tid >> 1) * 144 + (tid & 1) * 64;
#pragma unroll
        for (int j = 0; j < 4; j++) cp16(kd + j * 16, ks + j * 8);
        const __half* vs = Vp + (size_t)(kt * 128 + (tid >> 1)) * ldk + (tid & 1) * 32;
        uint32_t vd = sVa + buf * 18432u + (tid >> 1) * 144 + (tid & 1) * 64;
#pragma unroll
        for (int j = 0; j < 4; j++) cp16(vd + j * 16, vs + j * 8);
        if (tid < 32) {
            uint32_t mv = *(const uint32_t*)(padp + (size_t)kt * 128 + tid * 4);
            sMskp[buf * 32 + tid] = mv;
            uint32_t f = __reduce_or_sync(0xffffffffu, mv);
            if (tid == 0) sMskp[64 + buf] = f;
        }
    };
    issue_kv(0, 0);
    asm volatile("cp.async.commit_group;" ::: "memory");

    float m0 = -INFINITY, m1 = -INFINITY, l0 = 0.f, l1 = 0.f;
    float oacc[8][4];
#pragma unroll
    for (int j = 0; j < 8; j++)
#pragma unroll
        for (int r = 0; r < 4; r++) oacc[j][r] = 0.f;

    const int r0 = w * 16 + g, r1 = r0 + 8;

    for (int kt = 0; kt < nkt; ++kt) {
        const int buf = kt & 1;
        if (kt + 1 < nkt) {
            issue_kv(kt + 1, buf ^ 1);
            asm volatile("cp.async.commit_group;" ::: "memory");
            asm volatile("cp.async.wait_group 1;" ::: "memory");
        } else {
            asm volatile("cp.async.wait_group 0;" ::: "memory");
        }
        __syncthreads();

        float sacc[16][4];
#pragma unroll
        for (int ni = 0; ni < 16; ni++)
#pragma unroll
            for (int r = 0; r < 4; r++) sacc[ni][r] = 0.f;
        {
            const uint32_t kB = kL + buf * 18432u;
#pragma unroll
            for (int ks = 0; ks < 4; ks++) {
                uint32_t aq[4];
                ldsm4(aq, qL + ks * 32);
#pragma unroll
                for (int np = 0; np < 8; np++) {
                    uint32_t kv4[4];
                    ldsm4(kv4, kB + np * (16 * 144) + ks * 32);
                    mma_f16(sacc[2 * np],     aq, kv4);
                    mma_f16(sacc[2 * np + 1], aq, kv4 + 2);
                }
            }
        }

        const uint32_t pf = sMskp[64 + buf];
        const unsigned char* mb = (const unsigned char*)(sMskp + buf * 32);
        float tm0 = -INFINITY, tm1 = -INFINITY;
#pragma unroll
        for (int ni = 0; ni < 16; ni++) {
            float s0 = sacc[ni][0] * 0.125f, s1 = sacc[ni][1] * 0.125f;
            float s2 = sacc[ni][2] * 0.125f, s3 = sacc[ni][3] * 0.125f;
            const int c0 = ni * 8 + qc * 2;
            if (CAUSAL && kt == qt) {
                if (c0     > r0) s0 = -INFINITY;
                if (c0 + 1 > r0) s1 = -INFINITY;
                if (c0     > r1) s2 = -INFINITY;
                if (c0 + 1 > r1) s3 = -INFINITY;
            }
            if (pf) {
                if (mb[c0])     { s0 = -INFINITY; s2 = -INFINITY; }
                if (mb[c0 + 1]) { s1 = -INFINITY; s3 = -INFINITY; }
            }
            sacc[ni][0] = s0; sacc[ni][1] = s1; sacc[ni][2] = s2; sacc[ni][3] = s3;
            tm0 = fmaxf(tm0, fmaxf(s0, s1));
            tm1 = fmaxf(tm1, fmaxf(s2, s3));
        }
        tm0 = fmaxf(tm0, __shfl_xor_sync(0xffffffffu, tm0, 1));
        tm0 = fmaxf(tm0, __shfl_xor_sync(0xffffffffu, tm0, 2));
        tm1 = fmaxf(tm1, __shfl_xor_sync(0xffffffffu, tm1, 1));
        tm1 = fmaxf(tm1, __shfl_xor_sync(0xffffffffu, tm1, 2));
        const float mn0 = fmaxf(m0, tm0), mn1 = fmaxf(m1, tm1);

        float sum0 = 0.f, sum1 = 0.f;
#pragma unroll
        for (int ni = 0; ni < 16; ni++) {
            float p0 = __expf(sacc[ni][0] - mn0);
            float p1 = __expf(sacc[ni][1] - mn0);
            float p2 = __expf(sacc[ni][2] - mn1);
            float p3 = __expf(sacc[ni][3] - mn1);
            sacc[ni][0] = p0; sacc[ni][1] = p1; sacc[ni][2] = p2; sacc[ni][3] = p3;
            sum0 += p0 + p1; sum1 += p2 + p3;
        }
        sum0 += __shfl_xor_sync(0xffffffffu, sum0, 1);
        sum0 += __shfl_xor_sync(0xffffffffu, sum0, 2);
        sum1 += __shfl_xor_sync(0xffffffffu, sum1, 1);
        sum1 += __shfl_xor_sync(0xffffffffu, sum1, 2);

        const float sc0 = __expf(m0 - mn0), sc1 = __expf(m1 - mn1);
        l0 = l0 * sc0 + sum0;  l1 = l1 * sc1 + sum1;
        m0 = mn0;  m1 = mn1;
#pragma unroll
        for (int nj = 0; nj < 8; nj++) {
            oacc[nj][0] *= sc0; oacc[nj][1] *= sc0;
            oacc[nj][2] *= sc1; oacc[nj][3] *= sc1;
        }

        {
            const uint32_t vB = vL + buf * 18432u;
#pragma unroll
            for (int k2 = 0; k2 < 8; k2++) {
                uint32_t pa[4];
                pa[0] = packh2(sacc[2 * k2][0],     sacc[2 * k2][1]);
                pa[1] = packh2(sacc[2 * k2][2],     sacc[2 * k2][3]);
                pa[2] = packh2(sacc[2 * k2 + 1][0], sacc[2 * k2 + 1][1]);
                pa[3] = packh2(sacc[2 * k2 + 1][2], sacc[2 * k2 + 1][3]);
#pragma unroll
                for (int np = 0; np < 4; np++) {
                    uint32_t vv[4];
                    ldsm4t(vv, vB + k2 * (16 * 144) + np * 32);
                    mma_f16(oacc[2 * np],     pa, vv);
                    mma_f16(oacc[2 * np + 1], pa, vv + 2);
                }
            }
        }
        __syncthreads();
    }

    const float inv0 = 1.f / l0, inv1 = 1.f / l1;
    __half* orow0 = Op + (size_t)(qt * 128 + r0) * CC;
    __half* orow1 = orow0 + 8 * CC;
#pragma unroll
    for (int nj = 0; nj < 8; nj++) {
        *(__half2*)(orow0 + nj * 8 + qc * 2) =
            __floats2half2_rn(oacc[nj][0] * inv0, oacc[nj][1] * inv0);
        *(__half2*)(orow1 + nj * 8 + qc * 2) =
            __floats2half2_rn(oacc[nj][2] * inv1, oacc[nj][3] * inv1);
    }
}

// ============================ layernorm ==========================================
__device__ __forceinline__ float warpSum(float v) {
#pragma unroll
    for (int o = 16; o; o >>= 1) v += __shfl_xor_sync(0xffffffffu, v, o);
    return v;
}

template<bool DUALH>
__global__ void __launch_bounds__(256)
add_ln(const float* __restrict__ X, const float* __restrict__ R,
       const float* __restrict__ g, const float* __restrict__ be,
       float* __restrict__ out, __half* __restrict__ outh)
{
    const size_t row = blockIdx.x;
    const int tid = threadIdx.x;
    const int col = tid * 4;
    float4 xv = *(const float4*)(X + row * CC + col);
    float4 rv = *(const float4*)(R + row * CC + col);
    float4 v;
    v.x = xv.x + rv.x; v.y = xv.y + rv.y; v.z = xv.z + rv.z; v.w = xv.w + rv.w;

    __shared__ float sh1[8], sh2[8];
    float s = (v.x + v.y) + (v.z + v.w);
    float sq = v.x * v.x + v.y * v.y + v.z * v.z + v.w * v.w;
    s = warpSum(s); sq = warpSum(sq);
    if ((tid & 31) == 0) { sh1[tid >> 5] = s; sh2[tid >> 5] = sq; }
    __syncthreads();
    s  = (sh1[0] + sh1[1]) + (sh1[2] + sh1[3]) + (sh1[4] + sh1[5]) + (sh1[6] + sh1[7]);
    sq = (sh2[0] + sh2[1]) + (sh2[2] + sh2[3]) + (sh2[4] + sh2[5]) + (sh2[6] + sh2[7]);
    const float mean = s * (1.0f / CC);
    const float var = sq * (1.0f / CC) - mean * mean;
    const float rstd = rsqrtf(var + 1e-5f);

    float4 gg = *(const float4*)(g + col);
    float4 bb = *(const float4*)(be + col);
    float4 o;
    o.x = (v.x - mean) * rstd * gg.x + bb.x;
    o.y = (v.y - mean) * rstd * gg.y + bb.y;
    o.z = (v.z - mean) * rstd * gg.z + bb.z;
    o.w = (v.w - mean) * rstd * gg.w + bb.w;
    *(float4*)(out + row * CC + col) = o;
    if (DUALH) {
        *(__half2*)(outh + row * CC + col)     = __floats2half2_rn(o.x, o.y);
        *(__half2*)(outh + row * CC + col + 2) = __floats2half2_rn(o.z, o.w);
    }
}

// ------------------------------- launcher ---------------------------------------
extern "C" void kernel_launch(void* const* d_in, const int* in_sizes, int n_in,
                              void* d_out, int out_size)
{
    const float* x    = (const float*)d_in[0];
    const float* enc  = (const float*)d_in[1];
    const unsigned char* tmask = (const unsigned char*)d_in[2];
    const unsigned char* smask = (const unsigned char*)d_in[3];
    const float* Wq1 = (const float*)d_in[4];
    const float* Wk1 = (const float*)d_in[5];
    const float* Wv1 = (const float*)d_in[6];
    const float* Wo1 = (const float*)d_in[7];
    const float* ln1g = (const float*)d_in[8];
    const float* ln1b = (const float*)d_in[9];
    const float* Wq2 = (const float*)d_in[10];
    const float* Wk2 = (const float*)d_in[11];
    const float* Wv2 = (const float*)d_in[12];
    const float* Wo2 = (const float*)d_in[13];
    const float* ln2g = (const float*)d_in[14];
    const float* ln2b = (const float*)d_in[15];
    const float* Wf1 = (const float*)d_in[16];
    const float* bf1 = (const float*)d_in[17];
    const float* Wf2 = (const float*)d_in[18];
    const float* bf2 = (const float*)d_in[19];
    const float* ln3g = (const float*)d_in[20];
    const float* ln3b = (const float*)d_in[21];
    float* out = (float*)d_out;

    float *go, *gx1, *gx2;
    __half *gxh, *geh, *gqh, *gctxh, *gx1h, *gx2h, *gffh, *gwth;
    cudaGetSymbolAddress((void**)&go,  g_o);
    cudaGetSymbolAddress((void**)&gx1, g_x1);
    cudaGetSymbolAddress((void**)&gx2, g_x2);
    cudaGetSymbolAddress((void**)&gxh, g_xh);
    cudaGetSymbolAddress((void**)&geh, g_eh);
    cudaGetSymbolAddress((void**)&gqh, g_qh);
    cudaGetSymbolAddress((void**)&gctxh, g_ctxh);
    cudaGetSymbolAddress((void**)&gx1h, g_x1h);
    cudaGetSymbolAddress((void**)&gx2h, g_x2h);
    cudaGetSymbolAddress((void**)&gffh, g_ffh);
    cudaGetSymbolAddress((void**)&gwth, g_wth);

    __half* tq1 = gwth + 0u * 1048576u;   // tq1,tk1,tv1 contiguous -> [3072,1024]
    __half* tk1 = gwth + 1u * 1048576u;
    __half* tv1 = gwth + 2u * 1048576u;
    __half* to1 = gwth + 3u * 1048576u;
    __half* tq2 = gwth + 4u * 1048576u;
    __half* tk2 = gwth + 5u * 1048576u;   // tk2,tv2 contiguous -> [2048,1024]
    __half* tv2 = gwth + 6u * 1048576u;
    __half* to2 = gwth + 7u * 1048576u;
    __half* tf1 = gwth + 8u * 1048576u;              // [F, C]
    __half* tf2 = gwth + 8u * 1048576u + 4194304u;   // [C, F]

    auto* kProj  = gemm_mma<false, false, false>;   // fp32 out (-> add_ln)
    auto* kProjH = gemm_mma<false, false, true >;   // half out (-> flash / GEMM-A)
    auto* kFfn1  = gemm_mma<true,  true,  true >;   // bias+relu, half out
    auto* kFfn2  = gemm_mma<true,  false, false>;
    cudaFuncSetAttribute(kProj,  cudaFuncAttributeMaxDynamicSharedMemorySize, GSMEM);
    cudaFuncSetAttribute(kProjH, cudaFuncAttributeMaxDynamicSharedMemorySize, GSMEM);
    cudaFuncSetAttribute(kFfn1,  cudaFuncAttributeMaxDynamicSharedMemorySize, GSMEM);
    cudaFuncSetAttribute(kFfn2,  cudaFuncAttributeMaxDynamicSharedMemorySize, GSMEM);
    cudaFuncSetAttribute(flash_k<true>,  cudaFuncAttributeMaxDynamicSharedMemorySize, FSMEM);
    cudaFuncSetAttribute(flash_k<false>, cudaFuncAttributeMaxDynamicSharedMemorySize, FSMEM);

    const dim3 blk(256);
    const dim3 tblk(32, 8);

    // ---- fp16 conversion of external GEMM-A inputs (1 launch) ----
    Ptr2h p2;
    p2.s[0] = x;   p2.d[0] = gxh;
    p2.s[1] = enc; p2.d[1] = geh;
    round2h<<<dim3(MM * CC / 1024, 2), blk>>>(p2);

    // ---- weight transposes (K-major, fp16 B operands) ----
    Ptr8h p8;
    p8.s[0] = Wq1; p8.d[0] = tq1;  p8.s[1] = Wk1; p8.d[1] = tk1;
    p8.s[2] = Wv1; p8.d[2] = tv1;  p8.s[3] = Wo1; p8.d[3] = to1;
    p8.s[4] = Wq2; p8.d[4] = tq2;  p8.s[5] = Wk2; p8.d[5] = tk2;
    p8.s[6] = Wv2; p8.d[6] = tv2;  p8.s[7] = Wo2; p8.d[7] = to2;
    transpose8h<<<dim3(CC/32, CC/32, 8), tblk>>>(p8);
    transpose_w2<<<8192, tblk>>>(Wf1, tf1, Wf2, tf2);

    // persistent grids: min(ntiles, 2*148)
    const int NP = 296;
    const int tQKV = (3072/128) * (MM/128);   // 768
    const int tKV  = (2048/128) * (MM/128);   // 512
    const int tP   = (CC/128)   * (MM/128);   // 256
    const int tF1  = (FF/128)   * (MM/128);   // 1024
    const dim3 gFl (TT/128, BB*HH);           // (8, 64)
    const int nLn = MM;

    // ---- self-attention (causal) ----
    kProjH<<<NP, blk, GSMEM>>>(gxh, tq1, nullptr, gffh, CC, CC, CC, 3072, 3072/128, tQKV);
    flash_k<true><<<gFl, blk, FSMEM>>>(gffh, gffh + 1024, gffh + 2048, tmask, gctxh, 3072, 3072);
    kProj<<<tP, blk, GSMEM>>>(gctxh, to1, nullptr, go, CC, CC, CC, CC, CC/128, tP);
    add_ln<true><<<nLn, blk>>>(x, go, ln1g, ln1b, gx1, gx1h);

    // ---- cross-attention ----
    kProjH<<<tP, blk, GSMEM>>>(gx1h, tq2, nullptr, gqh, CC, CC, CC, CC, CC/128, tP);
    kProjH<<<NP, blk, GSMEM>>>(geh, tk2, nullptr, gffh, CC, CC, CC, 2048, 2048/128, tKV);
    flash_k<false><<<gFl, blk, FSMEM>>>(gqh, gffh, gffh + 1024, smask, gctxh, CC, 2048);
    kProj<<<tP, blk, GSMEM>>>(gctxh, to2, nullptr, go, CC, CC, CC, CC, CC/128, tP);
    add_ln<true><<<nLn, blk>>>(gx1, go, ln2g, ln2b, gx2, gx2h);

    // ---- FFN ----
    kFfn1<<<NP, blk, GSMEM>>>(gx2h, tf1, bf1, gffh, CC, CC, CC, FF, FF/128, tF1);
    kFfn2<<<tP, blk, GSMEM>>>(gffh, tf2, bf2, go, FF, FF, FF, CC, CC/128, tP);
    add_ln<false><<<nLn, blk>>>(gx2, go, ln3g, ln3b, out, nullptr);
}

// round 17
// speedup vs baseline: 1.0983x; 1.0653x over previous
#include <cuda_runtime.h>
#include <cuda_fp16.h>
#include <cstdint>
#include <cstddef>

// Problem constants
#define BB 4
#define TT 1024
#define CC 1024
#define HH 16
#define DH 64
#define FF 4096
#define MM (BB*TT)          // 4096 rows

// ---------------- scratch (device globals; no allocation allowed) ----------------
__device__ float  g_o  [(size_t)MM*CC];        // GEMM fp32 outputs (pre-LN)
__device__ float  g_x1 [(size_t)MM*CC];
__device__ float  g_x2 [(size_t)MM*CC];
__device__ __half g_xh [(size_t)MM*CC];        // half GEMM-A operands
__device__ __half g_eh [(size_t)MM*CC];
__device__ __half g_qh [(size_t)MM*CC];        // cross-attn Q (half, flash input)
__device__ __half g_kvh[(size_t)MM*2048];      // cross-attn K|V (half)
__device__ __half g_ctxh[(size_t)MM*CC];
__device__ __half g_x1h[(size_t)MM*CC];
__device__ __half g_x2h[(size_t)MM*CC];
__device__ __half g_ffh[(size_t)MM*FF];        // QKV / FFN1 half outputs
__device__ __half g_wth[8u*1024u*1024u + 2u*4096u*1024u];   // half weights (K-major)

// ============================ small helpers ======================================
__device__ __forceinline__ void mma_f16(float* d, const uint32_t* a, const uint32_t* b) {
    asm volatile(
        "mma.sync.aligned.m16n8k16.row.col.f32.f16.f16.f32 "
        "{%0,%1,%2,%3},{%4,%5,%6,%7},{%8,%9},{%0,%1,%2,%3};"
        : "+f"(d[0]), "+f"(d[1]), "+f"(d[2]), "+f"(d[3])
        : "r"(a[0]), "r"(a[1]), "r"(a[2]), "r"(a[3]),
          "r"(b[0]), "r"(b[1]));
}
__device__ __forceinline__ void ldsm4(uint32_t* r, uint32_t addr) {
    asm volatile("ldmatrix.sync.aligned.m8n8.x4.shared.b16 {%0,%1,%2,%3}, [%4];"
                 : "=r"(r[0]), "=r"(r[1]), "=r"(r[2]), "=r"(r[3]) : "r"(addr));
}
__device__ __forceinline__ void ldsm4t(uint32_t* r, uint32_t addr) {
    asm volatile("ldmatrix.sync.aligned.m8n8.x4.trans.shared.b16 {%0,%1,%2,%3}, [%4];"
                 : "=r"(r[0]), "=r"(r[1]), "=r"(r[2]), "=r"(r[3]) : "r"(addr));
}
__device__ __forceinline__ uint32_t smem_u32(const void* p) {
    uint32_t a;
    asm("{ .reg .u64 t; cvta.to.shared.u64 t, %1; cvt.u32.u64 %0, t; }" : "=r"(a) : "l"(p));
    return a;
}
__device__ __forceinline__ void cp16(uint32_t dst, const void* src) {
    asm volatile("cp.async.cg.shared.global [%0], [%1], 16;" :: "r"(dst), "l"(src));
}
__device__ __forceinline__ void bulk128(uint32_t dst, const void* src, uint32_t mbar) {
    asm volatile("cp.async.bulk.shared::cta.global.mbarrier::complete_tx::bytes "
                 "[%0], [%1], 128, [%2];"
                 :: "r"(dst), "l"(src), "r"(mbar) : "memory");
}
__device__ __forceinline__ void mbar_init1(uint32_t a) {
    asm volatile("mbarrier.init.shared.b64 [%0], 1;" :: "r"(a) : "memory");
}
__device__ __forceinline__ void mbar_expect(uint32_t a, uint32_t bytes) {
    asm volatile("mbarrier.arrive.expect_tx.shared.b64 _, [%0], %1;"
                 :: "r"(a), "r"(bytes) : "memory");
}
__device__ __forceinline__ void mbar_wait(uint32_t a, uint32_t ph) {
    uint32_t done;
    asm volatile("{\n\t.reg .pred p;\n\t"
                 "mbarrier.try_wait.parity.acquire.cta.shared::cta.b64 p, [%1], %2;\n\t"
                 "selp.b32 %0,1,0,p;\n\t}"
                 : "=r"(done) : "r"(a), "r"(ph) : "memory");
    if (!done) {
        asm volatile("{\n\t.reg .pred P1;\n\t"
                     "WL%=:\n\t"
                     "mbarrier.try_wait.parity.acquire.cta.shared::cta.b64 P1, [%0], %1, 0x989680;\n\t"
                     "@P1 bra.uni WD%=;\n\t"
                     "bra.uni WL%=;\n\t"
                     "WD%=:\n\t}"
                     :: "r"(a), "r"(ph) : "memory");
    }
}
__device__ __forceinline__ uint32_t packh2(float a, float b) {
    __half2 h = __floats2half2_rn(a, b);
    return *(uint32_t*)&h;
}

// =================== fp16 conversion copy (2 tensors, z-batched) =================
struct Ptr2h { const float* s[2]; __half* d[2]; };
__global__ void __launch_bounds__(256)
round2h(Ptr2h p)
{
    const float* in = p.s[blockIdx.y];
    __half* out = p.d[blockIdx.y];
    const size_t i = ((size_t)blockIdx.x * 256 + threadIdx.x) * 4;
    float4 v = *(const float4*)(in + i);
    *(__half2*)(out + i)     = __floats2half2_rn(v.x, v.y);
    *(__half2*)(out + i + 2) = __floats2half2_rn(v.z, v.w);
}

// ============ ALL weight transposes in one launch (16384 tiles, 1D) ==============
struct PtrW { const float* s[8]; __half* d[8];
              const float* wf1; __half* tf1; const float* wf2; __half* tf2; };

__global__ void __launch_bounds__(256)
transpose_all(PtrW ps)
{
    const int bid = blockIdx.x;
    const float* in;  __half* outp;  int R, C, bx, by;
    if (bid < 8192) {                 // 8 square [1024x1024] weights
        const int m = bid >> 10, t = bid & 1023;
        in = ps.s[m]; outp = ps.d[m]; R = CC; C = CC;
        bx = (t & 31) * 32; by = (t >> 5) * 32;
    } else if (bid < 12288) {         // Wf1 [1024x4096]
        const int t = bid - 8192;
        in = ps.wf1; outp = ps.tf1; R = CC; C = FF;
        bx = (t & 127) * 32; by = (t >> 7) * 32;
    } else {                          // Wf2 [4096x1024]
        const int t = bid - 12288;
        in = ps.wf2; outp = ps.tf2; R = FF; C = CC;
        bx = (t & 31) * 32; by = (t >> 5) * 32;
    }
    const int tx = threadIdx.x, ty = threadIdx.y;
    __shared__ float t[32][33];
    int x = bx + tx;
#pragma unroll
    for (int i = 0; i < 32; i += 8)
        t[ty + i][tx] = in[(size_t)(by + ty + i) * C + x];
    __syncthreads();
    x = by + tx;
#pragma unroll
    for (int i = 0; i < 32; i += 8)
        outp[(size_t)(bx + ty + i) * R + x] = __float2half_rn(t[tx][ty + i]);
}

// ================= persistent fp16 mma.sync GEMM =================================
#define G_LDPH 72                            // halfs per row (64 data + 8 pad)
#define G_STGH (256 * G_LDPH)                // halfs per stage (A128 + B128 rows)
#define GSMEM  (3 * G_STGH * 2 + 64)         // + 3 mbarriers (aligned)

template<bool BIAS, bool RELU, bool HOUT>
__global__ void __launch_bounds__(256, 2)
gemm_mma(const __half* __restrict__ A, const __half* __restrict__ Bt,
         const float* __restrict__ bias, void* __restrict__ Cv,
         int K, int lda, int ldb, int ldc, int nbx, int ntiles)
{
    extern __shared__ __half smh[];
    const int tid = threadIdx.x, wid = tid >> 5, lane = tid & 31;
    const int wr = wid >> 2, wc = wid & 3;      // 2 x 4 warps, 64x32 each
    const int g = lane >> 2, qc = lane & 3;

    const uint32_t smb = smem_u32(smh);
    const uint32_t mbar0 = smb + 3 * G_STGH * 2;
    const uint32_t sdst = smb + (uint32_t)tid * (G_LDPH * 2);

    const int l15 = lane & 15, l7 = lane & 7;
    const uint32_t aL = smb
        + (uint32_t)(((wr * 64 + l15) * G_LDPH + (lane >> 4) * 8) * 2);
    const uint32_t bL = smb + 128 * G_LDPH * 2
        + (uint32_t)(((wc * 32 + l7 + (lane >> 4) * 8) * G_LDPH + ((lane >> 3) & 1) * 8) * 2);

    const int nst = K >> 6;
    const int nmy = (ntiles - (int)blockIdx.x + (int)gridDim.x - 1) / (int)gridDim.x;
    if (nmy <= 0) return;
    const int S = nmy * nst;

    if (tid == 0) {
        mbar_init1(mbar0);
        mbar_init1(mbar0 + 8);
        mbar_init1(mbar0 + 16);
        asm volatile("fence.proxy.async.shared::cta;" ::: "memory");
    }
    __syncthreads();

    int ti = blockIdx.x, ki = 0;
    const __half* gsrc;
    {
        const int bx = (ti % nbx) << 7, by = (ti / nbx) << 7;
        gsrc = (tid < 128) ? (A  + (size_t)(by + tid) * lda)
                           : (Bt + (size_t)(bx + tid - 128) * ldb);
    }
    auto issue = [&](int slot) {
        if (tid == 0) mbar_expect(mbar0 + slot * 8, 32768u);
        bulk128(sdst + slot * (G_STGH * 2), gsrc + ki * 64, mbar0 + slot * 8);
        if (++ki == nst) {
            ki = 0;
            ti += gridDim.x;
            if (ti < ntiles) {
                const int bx = (ti % nbx) << 7, by = (ti / nbx) << 7;
                gsrc = (tid < 128) ? (A  + (size_t)(by + tid) * lda)
                                   : (Bt + (size_t)(bx + tid - 128) * ldb);
            }
        }
    };

    issue(0);
    if (S > 1) issue(1);

    int tc = blockIdx.x, kc = 0;
    int bxc = (tc % nbx) << 7, byc = (tc / nbx) << 7;
    int slot = 0;
    int ph0 = 0, ph1 = 0, ph2 = 0;

    float acc[4][4][4];
#pragma unroll
    for (int i = 0; i < 4; i++)
#pragma unroll
        for (int j = 0; j < 4; j++)
#pragma unroll
            for (int r = 0; r < 4; r++) acc[i][j][r] = 0.f;

    for (int j = 0; j < S; ++j) {
        if (slot == 0)      { mbar_wait(mbar0,      ph0); ph0 ^= 1; }
        else if (slot == 1) { mbar_wait(mbar0 + 8,  ph1); ph1 ^= 1; }
        else                { mbar_wait(mbar0 + 16, ph2); ph2 ^= 1; }
        __syncthreads();

        const uint32_t aB = aL + (uint32_t)slot * G_STGH * 2;
        const uint32_t bB = bL + (uint32_t)slot * G_STGH * 2;
#pragma unroll
        for (int ks = 0; ks < 4; ks++) {
            uint32_t av_[4][4], bv_[2][4];
#pragma unroll
            for (int mi = 0; mi < 4; mi++)
                ldsm4(av_[mi], aB + mi * (16 * G_LDPH * 2) + ks * 32);
#pragma unroll
            for (int np = 0; np < 2; np++)
                ldsm4(bv_[np], bB + np * (16 * G_LDPH * 2) + ks * 32);
#pragma unroll
            for (int mi = 0; mi < 4; mi++)
#pragma unroll
                for (int ni = 0; ni < 4; ni++)
                    mma_f16(acc[mi][ni], av_[mi], &bv_[ni >> 1][(ni & 1) * 2]);
        }

        if (j + 2 < S) issue(slot == 0 ? 2 : slot - 1);

        if (++kc == nst) {
#pragma unroll
            for (int mi = 0; mi < 4; mi++) {
                const int r = byc + wr * 64 + mi * 16 + g;
#pragma unroll
                for (int ni = 0; ni < 4; ni++) {
                    const int col = bxc + wc * 32 + ni * 8 + qc * 2;
                    float2 bv = make_float2(0.f, 0.f);
                    if (BIAS) bv = *(const float2*)(bias + col);
                    float2 v0, v1;
                    v0.x = acc[mi][ni][0] + bv.x;
                    v0.y = acc[mi][ni][1] + bv.y;
                    v1.x = acc[mi][ni][2] + bv.x;
                    v1.y = acc[mi][ni][3] + bv.y;
                    if (RELU) {
                        v0.x = fmaxf(v0.x, 0.f); v0.y = fmaxf(v0.y, 0.f);
                        v1.x = fmaxf(v1.x, 0.f); v1.y = fmaxf(v1.y, 0.f);
                    }
                    if (HOUT) {
                        __half* C = (__half*)Cv;
                        *(__half2*)(C + (size_t)r * ldc + col)       = __floats2half2_rn(v0.x, v0.y);
                        *(__half2*)(C + (size_t)(r + 8) * ldc + col) = __floats2half2_rn(v1.x, v1.y);
                    } else {
                        float* C = (float*)Cv;
                        *(float2*)(C + (size_t)r * ldc + col)       = v0;
                        *(float2*)(C + (size_t)(r + 8) * ldc + col) = v1;
                    }
                }
            }
            kc = 0;
            tc += gridDim.x;
            if (tc < ntiles) { bxc = (tc % nbx) << 7; byc = (tc / nbx) << 7; }
#pragma unroll
            for (int i = 0; i < 4; i++)
#pragma unroll
                for (int j2 = 0; j2 < 4; j2++)
#pragma unroll
                    for (int r = 0; r < 4; r++) acc[i][j2][r] = 0.f;
        }
        slot = (slot == 2) ? 0 : slot + 1;
    }
}

// ======== dual persistent GEMM: two descriptor-switched half-out GEMMs ===========
// tiles [0, nt0) -> GEMM0 (A0@B0 -> C0, nbx0); tiles [nt0, nt0+nt1) -> GEMM1.
// lda = ldb = 1024 for both. K = 1024. No bias/relu.
__global__ void __launch_bounds__(256, 2)
gemm_dual(const __half* __restrict__ A0, const __half* __restrict__ B0, __half* __restrict__ C0,
          int nbx0, int nt0,
          const __half* __restrict__ A1, const __half* __restrict__ B1, __half* __restrict__ C1,
          int nbx1, int nt1)
{
    extern __shared__ __half smh[];
    const int tid = threadIdx.x, wid = tid >> 5, lane = tid & 31;
    const int wr = wid >> 2, wc = wid & 3;
    const int g = lane >> 2, qc = lane & 3;

    const uint32_t smb = smem_u32(smh);
    const uint32_t mbar0 = smb + 3 * G_STGH * 2;
    const uint32_t sdst = smb + (uint32_t)tid * (G_LDPH * 2);

    const int l15 = lane & 15, l7 = lane & 7;
    const uint32_t aL = smb
        + (uint32_t)(((wr * 64 + l15) * G_LDPH + (lane >> 4) * 8) * 2);
    const uint32_t bL = smb + 128 * G_LDPH * 2
        + (uint32_t)(((wc * 32 + l7 + (lane >> 4) * 8) * G_LDPH + ((lane >> 3) & 1) * 8) * 2);

    const int nst = CC >> 6;                  // 16 stages (K = 1024)
    const int ntiles = nt0 + nt1;
    const int nmy = (ntiles - (int)blockIdx.x + (int)gridDim.x - 1) / (int)gridDim.x;
    if (nmy <= 0) return;
    const int S = nmy * nst;

    if (tid == 0) {
        mbar_init1(mbar0);
        mbar_init1(mbar0 + 8);
        mbar_init1(mbar0 + 16);
        asm volatile("fence.proxy.async.shared::cta;" ::: "memory");
    }
    __syncthreads();

    // ---- issue cursor ----
    int ti = blockIdx.x, ki = 0;
    const __half* gsrc;
    auto setsrc = [&](int t) {
        const bool d1 = t >= nt0;
        const int tt = d1 ? t - nt0 : t;
        const int nbx = d1 ? nbx1 : nbx0;
        const __half* Ap = d1 ? A1 : A0;
        const __half* Bp = d1 ? B1 : B0;
        const int bx = (tt % nbx) << 7, by = (tt / nbx) << 7;
        gsrc = (tid < 128) ? (Ap + (size_t)(by + tid) * CC)
                           : (Bp + (size_t)(bx + tid - 128) * CC);
    };
    setsrc(ti);
    auto issue = [&](int slot) {
        if (tid == 0) mbar_expect(mbar0 + slot * 8, 32768u);
        bulk128(sdst + slot * (G_STGH * 2), gsrc + ki * 64, mbar0 + slot * 8);
        if (++ki == nst) {
            ki = 0;
            ti += gridDim.x;
            if (ti < ntiles) setsrc(ti);
        }
    };

    issue(0);
    if (S > 1) issue(1);

    // ---- compute cursor ----
    int tc = blockIdx.x, kc = 0;
    int slot = 0;
    int ph0 = 0, ph1 = 0, ph2 = 0;

    float acc[4][4][4];
#pragma unroll
    for (int i = 0; i < 4; i++)
#pragma unroll
        for (int j = 0; j < 4; j++)
#pragma unroll
            for (int r = 0; r < 4; r++) acc[i][j][r] = 0.f;

    for (int j = 0; j < S; ++j) {
        if (slot == 0)      { mbar_wait(mbar0,      ph0); ph0 ^= 1; }
        else if (slot == 1) { mbar_wait(mbar0 + 8,  ph1); ph1 ^= 1; }
        else                { mbar_wait(mbar0 + 16, ph2); ph2 ^= 1; }
        __syncthreads();

        const uint32_t aB = aL + (uint32_t)slot * G_STGH * 2;
        const uint32_t bB = bL + (uint32_t)slot * G_STGH * 2;
#pragma unroll
        for (int ks = 0; ks < 4; ks++) {
            uint32_t av_[4][4], bv_[2][4];
#pragma unroll
            for (int mi = 0; mi < 4; mi++)
                ldsm4(av_[mi], aB + mi * (16 * G_LDPH * 2) + ks * 32);
#pragma unroll
            for (int np = 0; np < 2; np++)
                ldsm4(bv_[np], bB + np * (16 * G_LDPH * 2) + ks * 32);
#pragma unroll
            for (int mi = 0; mi < 4; mi++)
#pragma unroll
                for (int ni = 0; ni < 4; ni++)
                    mma_f16(acc[mi][ni], av_[mi], &bv_[ni >> 1][(ni & 1) * 2]);
        }

        if (j + 2 < S) issue(slot == 0 ? 2 : slot - 1);

        if (++kc == nst) {
            const bool d1 = tc >= nt0;
            const int tt = d1 ? tc - nt0 : tc;
            const int nbx = d1 ? nbx1 : nbx0;
            __half* Cp = d1 ? C1 : C0;
            const int ldc = nbx << 7;
            const int bxc = (tt % nbx) << 7, byc = (tt / nbx) << 7;
#pragma unroll
            for (int mi = 0; mi < 4; mi++) {
                const int r = byc + wr * 64 + mi * 16 + g;
#pragma unroll
                for (int ni = 0; ni < 4; ni++) {
                    const int col = bxc + wc * 32 + ni * 8 + qc * 2;
                    *(__half2*)(Cp + (size_t)r * ldc + col) =
                        __floats2half2_rn(acc[mi][ni][0], acc[mi][ni][1]);
                    *(__half2*)(Cp + (size_t)(r + 8) * ldc + col) =
                        __floats2half2_rn(acc[mi][ni][2], acc[mi][ni][3]);
                }
            }
            kc = 0;
            tc += gridDim.x;
#pragma unroll
            for (int i = 0; i < 4; i++)
#pragma unroll
                for (int j2 = 0; j2 < 4; j2++)
#pragma unroll
                    for (int r = 0; r < 4; r++) acc[i][j2][r] = 0.f;
        }
        slot = (slot == 2) ? 0 : slot + 1;
    }
}

// ====================== flash attention (fp16 mma, ldmatrix) =====================
#define FLB_K  18432
#define FLB_V  55296
#define FLB_M  92160
#define FSMEM  (92160 + 264)

template<bool CAUSAL>
__global__ void __launch_bounds__(256, 2)
flash_k(const __half* __restrict__ Qg, const __half* __restrict__ Kg,
        const __half* __restrict__ Vg, const unsigned char* __restrict__ padg,
        __half* __restrict__ Og, int ldq, int ldk)
{
    extern __shared__ __half smh[];
    const int tid = threadIdx.x, lane = tid & 31, w = tid >> 5;
    const int g = lane >> 2, qc = lane & 3;
    const int qt = blockIdx.x;
    const int z = blockIdx.y, b = z >> 4, h = z & 15;

    const __half* Qp = Qg + (size_t)b * TT * ldq + h * 64;
    const __half* Kp = Kg + (size_t)b * TT * ldk + h * 64;
    const __half* Vp = Vg + (size_t)b * TT * ldk + h * 64;
    const unsigned char* padp = padg + (size_t)b * TT;
    __half* Op = Og + (size_t)b * TT * CC + h * 64;

    const uint32_t sQa = smem_u32(smh);
    const uint32_t sKa = sQa + FLB_K;
    const uint32_t sVa = sQa + FLB_V;
    uint32_t* sMskp = (uint32_t*)((char*)smh + FLB_M);

    const int l15 = lane & 15, l7 = lane & 7;
    const uint32_t qL = sQa + (uint32_t)(((w * 16 + l15) * 72 + (lane >> 4) * 8) * 2);
    const uint32_t kL = sKa + (uint32_t)(((l7 + (lane >> 4) * 8) * 72 + ((lane >> 3) & 1) * 8) * 2);
    const uint32_t vL = sVa + (uint32_t)(((l7 + ((lane >> 3) & 1) * 8) * 72 + (lane >> 4) * 8) * 2);

    const int nkt = CAUSAL ? qt + 1 : (TT / 128);

    {
        const __half* qs = Qp + (size_t)(qt * 128 + (tid >> 1)) * ldq + (tid & 1) * 32;
        uint32_t qd = sQa + (tid >> 1) * 144 + (tid & 1) * 64;
#pragma unroll
        for (int j = 0; j < 4; j++) cp16(qd + j * 16, qs + j * 8);
    }
    auto issue_kv = [&](int kt, int buf) {
        const __half* ks = Kp + (size_t)(kt * 128 + (tid >> 1)) * ldk + (tid & 1) * 32;
        uint32_t kd = sKa + buf * 18432u + (tid >> 1) * 144 + (tid & 1) * 64;
#pragma unroll
        for (int j = 0; j < 4; j++) cp16(kd + j * 16, ks + j * 8);
        const __half* vs = Vp + (size_t)(kt * 128 + (tid >> 1)) * ldk + (tid & 1) * 32;
        uint32_t vd = sVa + buf * 18432u + (tid >> 1) * 144 + (tid & 1) * 64;
#pragma unroll
        for (int j = 0; j < 4; j++) cp16(vd + j * 16, vs + j * 8);
        if (tid < 32) {
            uint32_t mv = *(const uint32_t*)(padp + (size_t)kt * 128 + tid * 4);
            sMskp[buf * 32 + tid] = mv;
            uint32_t f = __reduce_or_sync(0xffffffffu, mv);
            if (tid == 0) sMskp[64 + buf] = f;
        }
    };
    issue_kv(0, 0);
    asm volatile("cp.async.commit_group;" ::: "memory");

    float m0 = -INFINITY, m1 = -INFINITY, l0 = 0.f, l1 = 0.f;
    float oacc[8][4];
#pragma unroll
    for (int j = 0; j < 8; j++)
#pragma unroll
        for (int r = 0; r < 4; r++) oacc[j][r] = 0.f;

    const int r0 = w * 16 + g, r1 = r0 + 8;

    for (int kt = 0; kt < nkt; ++kt) {
        const int buf = kt & 1;
        if (kt + 1 < nkt) {
            issue_kv(kt + 1, buf ^ 1);
            asm volatile("cp.async.commit_group;" ::: "memory");
            asm volatile("cp.async.wait_group 1;" ::: "memory");
        } else {
            asm volatile("cp.async.wait_group 0;" ::: "memory");
        }
        __syncthreads();

        float sacc[16][4];
#pragma unroll
        for (int ni = 0; ni < 16; ni++)
#pragma unroll
            for (int r = 0; r < 4; r++) sacc[ni][r] = 0.f;
        {
            const uint32_t kB = kL + buf * 18432u;
#pragma unroll
            for (int ks = 0; ks < 4; ks++) {
                uint32_t aq[4];
                ldsm4(aq, qL + ks * 32);
#pragma unroll
                for (int np = 0; np < 8; np++) {
                    uint32_t kv4[4];
                    ldsm4(kv4, kB + np * (16 * 144) + ks * 32);
                    mma_f16(sacc[2 * np],     aq, kv4);
                    mma_f16(sacc[2 * np + 1], aq, kv4 + 2);
                }
            }
        }

        const uint32_t pf = sMskp[64 + buf];
        const unsigned char* mb = (const unsigned char*)(sMskp + buf * 32);
        float tm0 = -INFINITY, tm1 = -INFINITY;
#pragma unroll
        for (int ni = 0; ni < 16; ni++) {
            float s0 = sacc[ni][0] * 0.125f, s1 = sacc[ni][1] * 0.125f;
            float s2 = sacc[ni][2] * 0.125f, s3 = sacc[ni][3] * 0.125f;
            const int c0 = ni * 8 + qc * 2;
            if (CAUSAL && kt == qt) {
                if (c0     > r0) s0 = -INFINITY;
                if (c0 + 1 > r0) s1 = -INFINITY;
                if (c0     > r1) s2 = -INFINITY;
                if (c0 + 1 > r1) s3 = -INFINITY;
            }
            if (pf) {
                if (mb[c0])     { s0 = -INFINITY; s2 = -INFINITY; }
                if (mb[c0 + 1]) { s1 = -INFINITY; s3 = -INFINITY; }
            }
            sacc[ni][0] = s0; sacc[ni][1] = s1; sacc[ni][2] = s2; sacc[ni][3] = s3;
            tm0 = fmaxf(tm0, fmaxf(s0, s1));
            tm1 = fmaxf(tm1, fmaxf(s2, s3));
        }
        tm0 = fmaxf(tm0, __shfl_xor_sync(0xffffffffu, tm0, 1));
        tm0 = fmaxf(tm0, __shfl_xor_sync(0xffffffffu, tm0, 2));
        tm1 = fmaxf(tm1, __shfl_xor_sync(0xffffffffu, tm1, 1));
        tm1 = fmaxf(tm1, __shfl_xor_sync(0xffffffffu, tm1, 2));
        const float mn0 = fmaxf(m0, tm0), mn1 = fmaxf(m1, tm1);

        float sum0 = 0.f, sum1 = 0.f;
#pragma unroll
        for (int ni = 0; ni < 16; ni++) {
            float p0 = __expf(sacc[ni][0] - mn0);
            float p1 = __expf(sacc[ni][1] - mn0);
            float p2 = __expf(sacc[ni][2] - mn1);
            float p3 = __expf(sacc[ni][3] - mn1);
            sacc[ni][0] = p0; sacc[ni][1] = p1; sacc[ni][2] = p2; sacc[ni][3] = p3;
            sum0 += p0 + p1; sum1 += p2 + p3;
        }
        sum0 += __shfl_xor_sync(0xffffffffu, sum0, 1);
        sum0 += __shfl_xor_sync(0xffffffffu, sum0, 2);
        sum1 += __shfl_xor_sync(0xffffffffu, sum1, 1);
        sum1 += __shfl_xor_sync(0xffffffffu, sum1, 2);

        const float sc0 = __expf(m0 - mn0), sc1 = __expf(m1 - mn1);
        l0 = l0 * sc0 + sum0;  l1 = l1 * sc1 + sum1;
        m0 = mn0;  m1 = mn1;
#pragma unroll
        for (int nj = 0; nj < 8; nj++) {
            oacc[nj][0] *= sc0; oacc[nj][1] *= sc0;
            oacc[nj][2] *= sc1; oacc[nj][3] *= sc1;
        }

        {
            const uint32_t vB = vL + buf * 18432u;
#pragma unroll
            for (int k2 = 0; k2 < 8; k2++) {
                uint32_t pa[4];
                pa[0] = packh2(sacc[2 * k2][0],     sacc[2 * k2][1]);
                pa[1] = packh2(sacc[2 * k2][2],     sacc[2 * k2][3]);
                pa[2] = packh2(sacc[2 * k2 + 1][0], sacc[2 * k2 + 1][1]);
                pa[3] = packh2(sacc[2 * k2 + 1][2], sacc[2 * k2 + 1][3]);
#pragma unroll
                for (int np = 0; np < 4; np++) {
                    uint32_t vv[4];
                    ldsm4t(vv, vB + k2 * (16 * 144) + np * 32);
                    mma_f16(oacc[2 * np],     pa, vv);
                    mma_f16(oacc[2 * np + 1], pa, vv + 2);
                }
            }
        }
        __syncthreads();
    }

    const float inv0 = 1.f / l0, inv1 = 1.f / l1;
    __half* orow0 = Op + (size_t)(qt * 128 + r0) * CC;
    __half* orow1 = orow0 + 8 * CC;
#pragma unroll
    for (int nj = 0; nj < 8; nj++) {
        *(__half2*)(orow0 + nj * 8 + qc * 2) =
            __floats2half2_rn(oacc[nj][0] * inv0, oacc[nj][1] * inv0);
        *(__half2*)(orow1 + nj * 8 + qc * 2) =
            __floats2half2_rn(oacc[nj][2] * inv1, oacc[nj][3] * inv1);
    }
}

// ============================ layernorm ==========================================
__device__ __forceinline__ float warpSum(float v) {
#pragma unroll
    for (int o = 16; o; o >>= 1) v += __shfl_xor_sync(0xffffffffu, v, o);
    return v;
}

template<bool DUALH>
__global__ void __launch_bounds__(256)
add_ln(const float* __restrict__ X, const float* __restrict__ R,
       const float* __restrict__ g, const float* __restrict__ be,
       float* __restrict__ out, __half* __restrict__ outh)
{
    const size_t row = blockIdx.x;
    const int tid = threadIdx.x;
    const int col = tid * 4;
    float4 xv = *(const float4*)(X + row * CC + col);
    float4 rv = *(const float4*)(R + row * CC + col);
    float4 v;
    v.x = xv.x + rv.x; v.y = xv.y + rv.y; v.z = xv.z + rv.z; v.w = xv.w + rv.w;

    __shared__ float sh1[8], sh2[8];
    float s = (v.x + v.y) + (v.z + v.w);
    float sq = v.x * v.x + v.y * v.y + v.z * v.z + v.w * v.w;
    s = warpSum(s); sq = warpSum(sq);
    if ((tid & 31) == 0) { sh1[tid >> 5] = s; sh2[tid >> 5] = sq; }
    __syncthreads();
    s  = (sh1[0] + sh1[1]) + (sh1[2] + sh1[3]) + (sh1[4] + sh1[5]) + (sh1[6] + sh1[7]);
    sq = (sh2[0] + sh2[1]) + (sh2[2] + sh2[3]) + (sh2[4] + sh2[5]) + (sh2[6] + sh2[7]);
    const float mean = s * (1.0f / CC);
    const float var = sq * (1.0f / CC) - mean * mean;
    const float rstd = rsqrtf(var + 1e-5f);

    float4 gg = *(const float4*)(g + col);
    float4 bb = *(const float4*)(be + col);
    float4 o;
    o.x = (v.x - mean) * rstd * gg.x + bb.x;
    o.y = (v.y - mean) * rstd * gg.y + bb.y;
    o.z = (v.z - mean) * rstd * gg.z + bb.z;
    o.w = (v.w - mean) * rstd * gg.w + bb.w;
    *(float4*)(out + row * CC + col) = o;
    if (DUALH) {
        *(__half2*)(outh + row * CC + col)     = __floats2half2_rn(o.x, o.y);
        *(__half2*)(outh + row * CC + col + 2) = __floats2half2_rn(o.z, o.w);
    }
}

// ------------------------------- launcher ---------------------------------------
extern "C" void kernel_launch(void* const* d_in, const int* in_sizes, int n_in,
                              void* d_out, int out_size)
{
    const float* x    = (const float*)d_in[0];
    const float* enc  = (const float*)d_in[1];
    const unsigned char* tmask = (const unsigned char*)d_in[2];
    const unsigned char* smask = (const unsigned char*)d_in[3];
    const float* Wq1 = (const float*)d_in[4];
    const float* Wk1 = (const float*)d_in[5];
    const float* Wv1 = (const float*)d_in[6];
    const float* Wo1 = (const float*)d_in[7];
    const float* ln1g = (const float*)d_in[8];
    const float* ln1b = (const float*)d_in[9];
    const float* Wq2 = (const float*)d_in[10];
    const float* Wk2 = (const float*)d_in[11];
    const float* Wv2 = (const float*)d_in[12];
    const float* Wo2 = (const float*)d_in[13];
    const float* ln2g = (const float*)d_in[14];
    const float* ln2b = (const float*)d_in[15];
    const float* Wf1 = (const float*)d_in[16];
    const float* bf1 = (const float*)d_in[17];
    const float* Wf2 = (const float*)d_in[18];
    const float* bf2 = (const float*)d_in[19];
    const float* ln3g = (const float*)d_in[20];
    const float* ln3b = (const float*)d_in[21];
    float* out = (float*)d_out;

    float *go, *gx1, *gx2;
    __half *gxh, *geh, *gqh, *gkvh, *gctxh, *gx1h, *gx2h, *gffh, *gwth;
    cudaGetSymbolAddress((void**)&go,  g_o);
    cudaGetSymbolAddress((void**)&gx1, g_x1);
    cudaGetSymbolAddress((void**)&gx2, g_x2);
    cudaGetSymbolAddress((void**)&gxh, g_xh);
    cudaGetSymbolAddress((void**)&geh, g_eh);
    cudaGetSymbolAddress((void**)&gqh, g_qh);
    cudaGetSymbolAddress((void**)&gkvh, g_kvh);
    cudaGetSymbolAddress((void**)&gctxh, g_ctxh);
    cudaGetSymbolAddress((void**)&gx1h, g_x1h);
    cudaGetSymbolAddress((void**)&gx2h, g_x2h);
    cudaGetSymbolAddress((void**)&gffh, g_ffh);
    cudaGetSymbolAddress((void**)&gwth, g_wth);

    __half* tq1 = gwth + 0u * 1048576u;   // tq1,tk1,tv1 contiguous -> [3072,1024]
    __half* tk1 = gwth + 1u * 1048576u;
    __half* tv1 = gwth + 2u * 1048576u;
    __half* to1 = gwth + 3u * 1048576u;
    __half* tq2 = gwth + 4u * 1048576u;
    __half* tk2 = gwth + 5u * 1048576u;   // tk2,tv2 contiguous -> [2048,1024]
    __half* tv2 = gwth + 6u * 1048576u;
    __half* to2 = gwth + 7u * 1048576u;
    __half* tf1 = gwth + 8u * 1048576u;              // [F, C]
    __half* tf2 = gwth + 8u * 1048576u + 4194304u;   // [C, F]

    auto* kProj  = gemm_mma<false, false, false>;   // fp32 out (-> add_ln)
    auto* kProjH = gemm_mma<false, false, true >;   // half out (-> flash / GEMM-A)
    auto* kFfn1  = gemm_mma<true,  true,  true >;   // bias+relu, half out
    auto* kFfn2  = gemm_mma<true,  false, false>;
    cudaFuncSetAttribute(kProj,  cudaFuncAttributeMaxDynamicSharedMemorySize, GSMEM);
    cudaFuncSetAttribute(kProjH, cudaFuncAttributeMaxDynamicSharedMemorySize, GSMEM);
    cudaFuncSetAttribute(kFfn1,  cudaFuncAttributeMaxDynamicSharedMemorySize, GSMEM);
    cudaFuncSetAttribute(kFfn2,  cudaFuncAttributeMaxDynamicSharedMemorySize, GSMEM);
    cudaFuncSetAttribute(gemm_dual, cudaFuncAttributeMaxDynamicSharedMemorySize, GSMEM);
    cudaFuncSetAttribute(flash_k<true>,  cudaFuncAttributeMaxDynamicSharedMemorySize, FSMEM);
    cudaFuncSetAttribute(flash_k<false>, cudaFuncAttributeMaxDynamicSharedMemorySize, FSMEM);

    const dim3 blk(256);
    const dim3 tblk(32, 8);

    // ---- fp16 conversion of external GEMM-A inputs (1 launch) ----
    Ptr2h p2;
    p2.s[0] = x;   p2.d[0] = gxh;
    p2.s[1] = enc; p2.d[1] = geh;
    round2h<<<dim3(MM * CC / 1024, 2), blk>>>(p2);

    // ---- ALL weight transposes (1 launch) ----
    PtrW pw;
    pw.s[0] = Wq1; pw.d[0] = tq1;  pw.s[1] = Wk1; pw.d[1] = tk1;
    pw.s[2] = Wv1; pw.d[2] = tv1;  pw.s[3] = Wo1; pw.d[3] = to1;
    pw.s[4] = Wq2; pw.d[4] = tq2;  pw.s[5] = Wk2; pw.d[5] = tk2;
    pw.s[6] = Wv2; pw.d[6] = tv2;  pw.s[7] = Wo2; pw.d[7] = to2;
    pw.wf1 = Wf1; pw.tf1 = tf1;  pw.wf2 = Wf2; pw.tf2 = tf2;
    transpose_all<<<16384, tblk>>>(pw);

    // persistent grids
    const int NP = 296;
    const int tQKV = (3072/128) * (MM/128);   // 768
    const int tKV  = (2048/128) * (MM/128);   // 512
    const int tP   = (CC/128)   * (MM/128);   // 256
    const int tF1  = (FF/128)   * (MM/128);   // 1024
    const dim3 gFl (TT/128, BB*HH);           // (8, 64)
    const int nLn = MM;

    // ---- fused self-QKV + cross-KV (one persistent launch, 1280 tiles) ----
    gemm_dual<<<NP, blk, GSMEM>>>(gxh, tq1, gffh, 3072/128, tQKV,
                                  geh, tk2, gkvh, 2048/128, tKV);

    // ---- self-attention (causal) ----
    flash_k<true><<<gFl, blk, FSMEM>>>(gffh, gffh + 1024, gffh + 2048, tmask, gctxh, 3072, 3072);
    kProj<<<tP, blk, GSMEM>>>(gctxh, to1, nullptr, go, CC, CC, CC, CC, CC/128, tP);
    add_ln<true><<<nLn, blk>>>(x, go, ln1g, ln1b, gx1, gx1h);

    // ---- cross-attention ----
    kProjH<<<tP, blk, GSMEM>>>(gx1h, tq2, nullptr, gqh, CC, CC, CC, CC, CC/128, tP);
    flash_k<false><<<gFl, blk, FSMEM>>>(gqh, gkvh, gkvh + 1024, smask, gctxh, CC, 2048);
    kProj<<<tP, blk, GSMEM>>>(gctxh, to2, nullptr, go, CC, CC, CC, CC, CC/128, tP);
    add_ln<true><<<nLn, blk>>>(gx1, go, ln2g, ln2b, gx2, gx2h);

    // ---- FFN ----
    kFfn1<<<NP, blk, GSMEM>>>(gx2h, tf1, bf1, gffh, CC, CC, CC, FF, FF/128, tF1);
    kFfn2<<<tP, blk, GSMEM>>>(gffh, tf2, bf2, go, FF, FF, FF, CC, CC/128, tP);
    add_ln<false><<<nLn, blk>>>(gx2, go, ln3g, ln3b, out, nullptr);
}